// round 1
// baseline (speedup 1.0000x reference)
#include <cuda_runtime.h>
#include <cuda_bf16.h>
#include <cstdint>

#define B   32
#define L   1024
#define D   256
#define INV_TEMP (1.0f/16.0f)

#define BM 128
#define BN 128
#define BK 16

__device__ __forceinline__ float neg_inf() { return __int_as_float(0xff800000); }

// ---------------------------------------------------------------------------
// Kernel 1: S = (Q @ Q^T), epilogue: s==0 -> -inf else s/16.  Written to attn.
// Grid: (L/BN, L/BM, B), 256 threads, 8x8 micro-tile per thread.
// ---------------------------------------------------------------------------
__global__ void __launch_bounds__(256) gemm_qqt_kernel(const float* __restrict__ q,
                                                       float* __restrict__ attn) {
    const int b  = blockIdx.z;
    const int m0 = blockIdx.y * BM;
    const int n0 = blockIdx.x * BN;
    const float* Q = q    + (size_t)b * L * D;
    float*       A = attn + (size_t)b * L * L;

    __shared__ float As[BK][BM + 4];
    __shared__ float Bs[BK][BN + 4];

    const int tid = threadIdx.x;
    const int tn  = tid & 15;   // 0..15
    const int tm  = tid >> 4;   // 0..15

    const int lrow = tid >> 2;        // 0..63
    const int lcol = (tid & 3) * 4;   // 0,4,8,12

    float acc[8][8];
    #pragma unroll
    for (int i = 0; i < 8; i++)
        #pragma unroll
        for (int j = 0; j < 8; j++) acc[i][j] = 0.0f;

    for (int kt = 0; kt < D; kt += BK) {
        #pragma unroll
        for (int r = 0; r < 2; r++) {
            const int row = lrow + r * 64;
            float4 va = *(const float4*)(Q + (size_t)(m0 + row) * D + kt + lcol);
            As[lcol + 0][row] = va.x; As[lcol + 1][row] = va.y;
            As[lcol + 2][row] = va.z; As[lcol + 3][row] = va.w;
            float4 vb = *(const float4*)(Q + (size_t)(n0 + row) * D + kt + lcol);
            Bs[lcol + 0][row] = vb.x; Bs[lcol + 1][row] = vb.y;
            Bs[lcol + 2][row] = vb.z; Bs[lcol + 3][row] = vb.w;
        }
        __syncthreads();

        #pragma unroll
        for (int k = 0; k < BK; k++) {
            float ra[8], rb[8];
            *(float4*)&ra[0] = *(const float4*)&As[k][tm * 8];
            *(float4*)&ra[4] = *(const float4*)&As[k][tm * 8 + 4];
            *(float4*)&rb[0] = *(const float4*)&Bs[k][tn * 8];
            *(float4*)&rb[4] = *(const float4*)&Bs[k][tn * 8 + 4];
            #pragma unroll
            for (int i = 0; i < 8; i++)
                #pragma unroll
                for (int j = 0; j < 8; j++)
                    acc[i][j] = fmaf(ra[i], rb[j], acc[i][j]);
        }
        __syncthreads();
    }

    // Epilogue: data-dependent mask, then temperature scale.
    #pragma unroll
    for (int i = 0; i < 8; i++) {
        float* orow = A + (size_t)(m0 + tm * 8 + i) * L + n0 + tn * 8;
        #pragma unroll
        for (int j = 0; j < 8; j += 4) {
            float4 v;
            v.x = (acc[i][j + 0] == 0.0f) ? neg_inf() : acc[i][j + 0] * INV_TEMP;
            v.y = (acc[i][j + 1] == 0.0f) ? neg_inf() : acc[i][j + 1] * INV_TEMP;
            v.z = (acc[i][j + 2] == 0.0f) ? neg_inf() : acc[i][j + 2] * INV_TEMP;
            v.w = (acc[i][j + 3] == 0.0f) ? neg_inf() : acc[i][j + 3] * INV_TEMP;
            *(float4*)(orow + j) = v;
        }
    }
}

// ---------------------------------------------------------------------------
// Kernel 2: rowwise softmax in-place on attn. One block per row (B*L rows).
// 256 threads, each owns one float4 (L=1024). All-(-inf) rows -> zeros.
// ---------------------------------------------------------------------------
__global__ void __launch_bounds__(256) softmax_kernel(float* __restrict__ attn) {
    float* p = attn + (size_t)blockIdx.x * L;
    const int tid = threadIdx.x;

    float4 v = ((const float4*)p)[tid];
    float m = fmaxf(fmaxf(v.x, v.y), fmaxf(v.z, v.w));
    #pragma unroll
    for (int o = 16; o > 0; o >>= 1) m = fmaxf(m, __shfl_xor_sync(0xffffffffu, m, o));

    __shared__ float smem[8];
    __shared__ float stat;
    const int wid = tid >> 5, lid = tid & 31;
    if (lid == 0) smem[wid] = m;
    __syncthreads();
    if (tid == 0) {
        float mm = smem[0];
        #pragma unroll
        for (int i = 1; i < 8; i++) mm = fmaxf(mm, smem[i]);
        stat = mm;
    }
    __syncthreads();
    const float rmax = stat;

    if (rmax == neg_inf()) {
        // Entire row masked: reference produces NaN -> 0.
        ((float4*)p)[tid] = make_float4(0.f, 0.f, 0.f, 0.f);
        return;
    }

    float4 e;
    e.x = __expf(v.x - rmax);
    e.y = __expf(v.y - rmax);
    e.z = __expf(v.z - rmax);
    e.w = __expf(v.w - rmax);
    float s = (e.x + e.y) + (e.z + e.w);
    #pragma unroll
    for (int o = 16; o > 0; o >>= 1) s += __shfl_xor_sync(0xffffffffu, s, o);
    if (lid == 0) smem[wid] = s;
    __syncthreads();
    if (tid == 0) {
        float ss = smem[0];
        #pragma unroll
        for (int i = 1; i < 8; i++) ss += smem[i];
        stat = 1.0f / ss;
    }
    __syncthreads();
    const float inv = stat;

    e.x *= inv; e.y *= inv; e.z *= inv; e.w *= inv;
    ((float4*)p)[tid] = e;
}

// ---------------------------------------------------------------------------
// Kernel 3: O = P @ Q   (M=L, K=L, N=D). Grid: (D/BN, L/BM, B).
// ---------------------------------------------------------------------------
__global__ void __launch_bounds__(256) gemm_pv_kernel(const float* __restrict__ attn,
                                                      const float* __restrict__ q,
                                                      float* __restrict__ out) {
    const int b  = blockIdx.z;
    const int m0 = blockIdx.y * BM;
    const int n0 = blockIdx.x * BN;
    const float* P = attn + (size_t)b * L * L;
    const float* V = q    + (size_t)b * L * D;
    float*       O = out  + (size_t)b * L * D;

    __shared__ float As[BK][BM + 4];  // transposed P tile
    __shared__ float Bs[BK][BN + 4];  // direct V tile

    const int tid = threadIdx.x;
    const int tn  = tid & 15;
    const int tm  = tid >> 4;

    const int lrow = tid >> 2;        // 0..63
    const int lcol = (tid & 3) * 4;   // 0,4,8,12
    const int brow = tid >> 5;        // 0..7
    const int bcol = (tid & 31) * 4;  // 0..124

    float acc[8][8];
    #pragma unroll
    for (int i = 0; i < 8; i++)
        #pragma unroll
        for (int j = 0; j < 8; j++) acc[i][j] = 0.0f;

    for (int kt = 0; kt < L; kt += BK) {
        #pragma unroll
        for (int r = 0; r < 2; r++) {
            const int row = lrow + r * 64;
            float4 va = *(const float4*)(P + (size_t)(m0 + row) * L + kt + lcol);
            As[lcol + 0][row] = va.x; As[lcol + 1][row] = va.y;
            As[lcol + 2][row] = va.z; As[lcol + 3][row] = va.w;
        }
        #pragma unroll
        for (int r = 0; r < 2; r++) {
            const int krow = brow + r * 8;
            *(float4*)&Bs[krow][bcol] =
                *(const float4*)(V + (size_t)(kt + krow) * D + n0 + bcol);
        }
        __syncthreads();

        #pragma unroll
        for (int k = 0; k < BK; k++) {
            float ra[8], rb[8];
            *(float4*)&ra[0] = *(const float4*)&As[k][tm * 8];
            *(float4*)&ra[4] = *(const float4*)&As[k][tm * 8 + 4];
            *(float4*)&rb[0] = *(const float4*)&Bs[k][tn * 8];
            *(float4*)&rb[4] = *(const float4*)&Bs[k][tn * 8 + 4];
            #pragma unroll
            for (int i = 0; i < 8; i++)
                #pragma unroll
                for (int j = 0; j < 8; j++)
                    acc[i][j] = fmaf(ra[i], rb[j], acc[i][j]);
        }
        __syncthreads();
    }

    #pragma unroll
    for (int i = 0; i < 8; i++) {
        float* orow = O + (size_t)(m0 + tm * 8 + i) * D + n0 + tn * 8;
        #pragma unroll
        for (int j = 0; j < 8; j += 4) {
            float4 v;
            v.x = acc[i][j + 0]; v.y = acc[i][j + 1];
            v.z = acc[i][j + 2]; v.w = acc[i][j + 3];
            *(float4*)(orow + j) = v;
        }
    }
}

// ---------------------------------------------------------------------------
// Launch. d_out layout: [output (B*L*D)] then [attn (B*L*L)], return order.
// ---------------------------------------------------------------------------
extern "C" void kernel_launch(void* const* d_in, const int* in_sizes, int n_in,
                              void* d_out, int out_size) {
    const float* q = (const float*)d_in[0];
    float* out  = (float*)d_out;                       // B*L*D
    float* attn = (float*)d_out + (size_t)B * L * D;   // B*L*L

    dim3 g1(L / BN, L / BM, B);     // (8, 8, 32)
    gemm_qqt_kernel<<<g1, 256>>>(q, attn);

    softmax_kernel<<<B * L, 256>>>(attn);

    dim3 g3(D / BN, L / BM, B);     // (2, 8, 32)
    gemm_pv_kernel<<<g3, 256>>>(attn, q, out);
}

// round 3
// speedup vs baseline: 1.6645x; 1.6645x over previous
#include <cuda_runtime.h>
#include <cuda_bf16.h>
#include <cstdint>

#define B   32
#define L   1024
#define D   256
#define INV_TEMP (1.0f/16.0f)

// ---------------------------------------------------------------------------
// Scratch (static device arrays; runtime allocation is forbidden)
// ---------------------------------------------------------------------------
__device__ __nv_bfloat16 g_qh [B * L * D];   // q hi          [B,L,D]
__device__ __nv_bfloat16 g_ql [B * L * D];   // q lo          [B,L,D]
__device__ __nv_bfloat16 g_qth[B * D * L];   // q^T hi        [B,D,L]
__device__ __nv_bfloat16 g_qtl[B * D * L];   // q^T lo        [B,D,L]
__device__ __nv_bfloat16 g_ph [B * L * L];   // softmax(P) hi [B,L,L]
__device__ __nv_bfloat16 g_pl [B * L * L];   // softmax(P) lo [B,L,L]

__device__ __forceinline__ float neg_inf() { return __int_as_float(0xff800000); }

__device__ __forceinline__ uint32_t smem_to_u32(const void* p) {
    uint32_t a;
    asm("{ .reg .u64 t; cvta.to.shared.u64 t, %1; cvt.u32.u64 %0, t; }" : "=r"(a) : "l"(p));
    return a;
}

// SW128 swizzle: XOR bits [6:4] with bits [9:7] (keeps 16B chunks intact)
#define SWZ(x) ((x) ^ (((x) >> 3) & 0x70))

__device__ __forceinline__ void ldsm_x4(uint32_t& r0, uint32_t& r1, uint32_t& r2, uint32_t& r3,
                                        uint32_t addr) {
    asm volatile("ldmatrix.sync.aligned.m8n8.x4.shared.b16 {%0,%1,%2,%3}, [%4];"
                 : "=r"(r0), "=r"(r1), "=r"(r2), "=r"(r3) : "r"(addr));
}

__device__ __forceinline__ void mma_bf16(float& c0, float& c1, float& c2, float& c3,
                                         uint32_t a0, uint32_t a1, uint32_t a2, uint32_t a3,
                                         uint32_t b0, uint32_t b1) {
    asm volatile("mma.sync.aligned.m16n8k16.row.col.f32.bf16.bf16.f32 "
                 "{%0,%1,%2,%3}, {%4,%5,%6,%7}, {%8,%9}, {%0,%1,%2,%3};"
                 : "+f"(c0), "+f"(c1), "+f"(c2), "+f"(c3)
                 : "r"(a0), "r"(a1), "r"(a2), "r"(a3), "r"(b0), "r"(b1));
}

// ---------------------------------------------------------------------------
// Kernel A: split q -> bf16 hi/lo + transposed hi/lo copies.
// grid (D/32, L/32, B), block (32, 8)
// ---------------------------------------------------------------------------
__global__ void __launch_bounds__(256) split_q_kernel(const float* __restrict__ q) {
    const int b  = blockIdx.z;
    const int d0 = blockIdx.x * 32;
    const int l0 = blockIdx.y * 32;
    const float* Q = q + (size_t)b * L * D;
    __shared__ float t[32][33];
    const int tx = threadIdx.x, ty = threadIdx.y;

    #pragma unroll
    for (int i = 0; i < 4; i++) {
        const int r = ty + i * 8;
        const float v = Q[(size_t)(l0 + r) * D + d0 + tx];
        t[r][tx] = v;
        __nv_bfloat16 h  = __float2bfloat16(v);
        __nv_bfloat16 lo = __float2bfloat16(v - __bfloat162float(h));
        const size_t idx = (size_t)b * L * D + (size_t)(l0 + r) * D + d0 + tx;
        g_qh[idx] = h;
        g_ql[idx] = lo;
    }
    __syncthreads();
    #pragma unroll
    for (int i = 0; i < 4; i++) {
        const int r = ty + i * 8;
        const float v = t[tx][r];                       // = Q[l0+tx, d0+r]
        __nv_bfloat16 h  = __float2bfloat16(v);
        __nv_bfloat16 lo = __float2bfloat16(v - __bfloat162float(h));
        const size_t idx = (size_t)b * D * L + (size_t)(d0 + r) * L + l0 + tx;
        g_qth[idx] = h;
        g_qtl[idx] = lo;
    }
}

// ---------------------------------------------------------------------------
// mma.sync split-bf16 GEMM: C[m,n] = sum_k A[m,k]*B[n,k]  (both K-major)
// CTA tile 128x128, 8 warps in 4x2 (warp tile 32x64), K chunk 64.
// 3-term split: Ah@Bh + Ah@Bl + Al@Bh.
// MASK: c==0 -> -inf else c/16.
// ---------------------------------------------------------------------------
#define OFF_AH 0
#define OFF_AL 16384
#define OFF_BH 32768
#define OFF_BL 49152
#define GEMM_SMEM 65536

__device__ __forceinline__ void load_tile64(const __nv_bfloat16* __restrict__ src,
                                            int row0, int ld, int k0,
                                            char* smem_tile, int tid) {
    #pragma unroll
    for (int i = 0; i < 4; i++) {
        const int chunk = tid + i * 256;        // 0..1023 (16B chunks)
        const int row = chunk >> 3;             // 0..127
        const int c16 = chunk & 7;              // 0..7
        uint4 v = *(const uint4*)(src + (size_t)(row0 + row) * ld + k0 + c16 * 8);
        const uint32_t boff = row * 128 + c16 * 16;
        *(uint4*)(smem_tile + SWZ(boff)) = v;
    }
}

template <bool MASK>
__global__ void __launch_bounds__(256)
gemm_tc_kernel(const __nv_bfloat16* __restrict__ Ah, const __nv_bfloat16* __restrict__ Al,
               const __nv_bfloat16* __restrict__ Bh, const __nv_bfloat16* __restrict__ Bl,
               float* __restrict__ C,
               int lda, int ldb, int ldc, int Ktot,
               size_t sA, size_t sB, size_t sC) {
    extern __shared__ char smem[];
    const uint32_t sb = smem_to_u32(smem);
    const int tid = threadIdx.x, wid = tid >> 5, lid = tid & 31;
    const int b  = blockIdx.z;
    const int m0 = blockIdx.y * 128;
    const int n0 = blockIdx.x * 128;

    const __nv_bfloat16* pAh = Ah + (size_t)b * sA;
    const __nv_bfloat16* pAl = Al + (size_t)b * sA;
    const __nv_bfloat16* pBh = Bh + (size_t)b * sB;
    const __nv_bfloat16* pBl = Bl + (size_t)b * sB;

    const int wm = wid & 3;          // 0..3 -> 32-row group
    const int wn = wid >> 2;         // 0..1 -> 64-col group
    const int rowbase = wm * 32;
    const int colbase = wn * 64;

    // ldmatrix lane addressing pieces (within a tile)
    const int lrow = lid & 15;                   // row within 16-row block
    const uint32_t lkoff = (uint32_t)((lid >> 4) * 16);  // 0 or 16 bytes (k 0/8)

    float acc[2][8][4];
    #pragma unroll
    for (int mt = 0; mt < 2; mt++)
        #pragma unroll
        for (int nt = 0; nt < 8; nt++)
            #pragma unroll
            for (int r = 0; r < 4; r++) acc[mt][nt][r] = 0.0f;

    const int nch = Ktot >> 6;
    for (int c = 0; c < nch; c++) {
        const int k0 = c << 6;
        load_tile64(pAh, m0, lda, k0, smem + OFF_AH, tid);
        load_tile64(pAl, m0, lda, k0, smem + OFF_AL, tid);
        load_tile64(pBh, n0, ldb, k0, smem + OFF_BH, tid);
        load_tile64(pBl, n0, ldb, k0, smem + OFF_BL, tid);
        __syncthreads();

        #pragma unroll
        for (int t = 0; t < 3; t++) {
            const uint32_t abase = sb + (t == 2 ? OFF_AL : OFF_AH);
            const uint32_t bbase = sb + (t == 1 ? OFF_BL : OFF_BH);
            #pragma unroll
            for (int ks = 0; ks < 4; ks++) {
                const uint32_t kb = (uint32_t)(ks * 32) + lkoff;
                uint32_t a[2][4];
                #pragma unroll
                for (int mt = 0; mt < 2; mt++) {
                    const uint32_t boff = (uint32_t)((rowbase + mt * 16 + lrow) * 128) + kb;
                    ldsm_x4(a[mt][0], a[mt][1], a[mt][2], a[mt][3], abase + SWZ(boff));
                }
                uint32_t bf[4][4];
                #pragma unroll
                for (int np = 0; np < 4; np++) {
                    const uint32_t boff = (uint32_t)((colbase + np * 16 + lrow) * 128) + kb;
                    ldsm_x4(bf[np][0], bf[np][1], bf[np][2], bf[np][3], bbase + SWZ(boff));
                }
                #pragma unroll
                for (int mt = 0; mt < 2; mt++)
                    #pragma unroll
                    for (int np = 0; np < 4; np++) {
                        mma_bf16(acc[mt][np*2+0][0], acc[mt][np*2+0][1],
                                 acc[mt][np*2+0][2], acc[mt][np*2+0][3],
                                 a[mt][0], a[mt][1], a[mt][2], a[mt][3],
                                 bf[np][0], bf[np][2]);
                        mma_bf16(acc[mt][np*2+1][0], acc[mt][np*2+1][1],
                                 acc[mt][np*2+1][2], acc[mt][np*2+1][3],
                                 a[mt][0], a[mt][1], a[mt][2], a[mt][3],
                                 bf[np][1], bf[np][3]);
                    }
            }
        }
        __syncthreads();
    }

    // Epilogue: each thread owns 2x float2 per (mt, nt) mma tile.
    float* pC = C + (size_t)b * sC;
    const int trow = lid >> 2;          // 0..7
    const int tcol = (lid & 3) * 2;     // 0,2,4,6
    #pragma unroll
    for (int mt = 0; mt < 2; mt++) {
        #pragma unroll
        for (int nt = 0; nt < 8; nt++) {
            const int row = m0 + rowbase + mt * 16 + trow;
            const int col = n0 + colbase + nt * 8 + tcol;
            float v0 = acc[mt][nt][0], v1 = acc[mt][nt][1];
            float v2 = acc[mt][nt][2], v3 = acc[mt][nt][3];
            if (MASK) {
                v0 = (v0 == 0.0f) ? neg_inf() : v0 * INV_TEMP;
                v1 = (v1 == 0.0f) ? neg_inf() : v1 * INV_TEMP;
                v2 = (v2 == 0.0f) ? neg_inf() : v2 * INV_TEMP;
                v3 = (v3 == 0.0f) ? neg_inf() : v3 * INV_TEMP;
            }
            *(float2*)(pC + (size_t)row * ldc + col)       = make_float2(v0, v1);
            *(float2*)(pC + (size_t)(row + 8) * ldc + col) = make_float2(v2, v3);
        }
    }
}

// ---------------------------------------------------------------------------
// Kernel C: rowwise softmax in-place on attn; also emits P hi/lo bf16.
// One block per row (B*L rows), 256 threads.
// ---------------------------------------------------------------------------
__global__ void __launch_bounds__(256) softmax_kernel(float* __restrict__ attn) {
    const size_t row = blockIdx.x;
    float* p = attn + row * L;
    __nv_bfloat16* ph = g_ph + row * L;
    __nv_bfloat16* pl = g_pl + row * L;
    const int tid = threadIdx.x;

    float4 v = ((const float4*)p)[tid];
    float m = fmaxf(fmaxf(v.x, v.y), fmaxf(v.z, v.w));
    #pragma unroll
    for (int o = 16; o > 0; o >>= 1) m = fmaxf(m, __shfl_xor_sync(0xffffffffu, m, o));

    __shared__ float smem[8];
    __shared__ float stat;
    const int wid = tid >> 5, lid = tid & 31;
    if (lid == 0) smem[wid] = m;
    __syncthreads();
    if (tid == 0) {
        float mm = smem[0];
        #pragma unroll
        for (int i = 1; i < 8; i++) mm = fmaxf(mm, smem[i]);
        stat = mm;
    }
    __syncthreads();
    const float rmax = stat;

    if (rmax == neg_inf()) {
        ((float4*)p)[tid] = make_float4(0.f, 0.f, 0.f, 0.f);
        const uint2 z = make_uint2(0u, 0u);
        ((uint2*)ph)[tid] = z;
        ((uint2*)pl)[tid] = z;
        return;
    }

    float4 e;
    e.x = __expf(v.x - rmax); e.y = __expf(v.y - rmax);
    e.z = __expf(v.z - rmax); e.w = __expf(v.w - rmax);
    float s = (e.x + e.y) + (e.z + e.w);
    #pragma unroll
    for (int o = 16; o > 0; o >>= 1) s += __shfl_xor_sync(0xffffffffu, s, o);
    if (lid == 0) smem[wid] = s;
    __syncthreads();
    if (tid == 0) {
        float ss = smem[0];
        #pragma unroll
        for (int i = 1; i < 8; i++) ss += smem[i];
        stat = 1.0f / ss;
    }
    __syncthreads();
    const float inv = stat;
    e.x *= inv; e.y *= inv; e.z *= inv; e.w *= inv;
    ((float4*)p)[tid] = e;

    __nv_bfloat16 h0 = __float2bfloat16(e.x), h1 = __float2bfloat16(e.y);
    __nv_bfloat16 h2 = __float2bfloat16(e.z), h3 = __float2bfloat16(e.w);
    __nv_bfloat16 l0 = __float2bfloat16(e.x - __bfloat162float(h0));
    __nv_bfloat16 l1 = __float2bfloat16(e.y - __bfloat162float(h1));
    __nv_bfloat16 l2 = __float2bfloat16(e.z - __bfloat162float(h2));
    __nv_bfloat16 l3 = __float2bfloat16(e.w - __bfloat162float(h3));
    __nv_bfloat162 hp0, hp1, lp0, lp1;
    hp0.x = h0; hp0.y = h1; hp1.x = h2; hp1.y = h3;
    lp0.x = l0; lp0.y = l1; lp1.x = l2; lp1.y = l3;
    ((__nv_bfloat162*)ph)[tid * 2]     = hp0;
    ((__nv_bfloat162*)ph)[tid * 2 + 1] = hp1;
    ((__nv_bfloat162*)pl)[tid * 2]     = lp0;
    ((__nv_bfloat162*)pl)[tid * 2 + 1] = lp1;
}

// ---------------------------------------------------------------------------
// Launch. d_out layout: [output (B*L*D)] then [attn (B*L*L)].
// ---------------------------------------------------------------------------
extern "C" void kernel_launch(void* const* d_in, const int* in_sizes, int n_in,
                              void* d_out, int out_size) {
    const float* q = (const float*)d_in[0];
    float* out  = (float*)d_out;
    float* attn = (float*)d_out + (size_t)B * L * D;

    void *qh, *ql, *qth, *qtl, *ph, *pl;
    cudaGetSymbolAddress(&qh,  g_qh);
    cudaGetSymbolAddress(&ql,  g_ql);
    cudaGetSymbolAddress(&qth, g_qth);
    cudaGetSymbolAddress(&qtl, g_qtl);
    cudaGetSymbolAddress(&ph,  g_ph);
    cudaGetSymbolAddress(&pl,  g_pl);

    cudaFuncSetAttribute(gemm_tc_kernel<true>,  cudaFuncAttributeMaxDynamicSharedMemorySize, GEMM_SMEM);
    cudaFuncSetAttribute(gemm_tc_kernel<false>, cudaFuncAttributeMaxDynamicSharedMemorySize, GEMM_SMEM);

    // 1) split q
    dim3 gs(D / 32, L / 32, B);
    split_q_kernel<<<gs, dim3(32, 8)>>>(q);

    // 2) S = Q@Q^T (split bf16) + mask/scale -> attn
    dim3 g1(L / 128, L / 128, B);
    gemm_tc_kernel<true><<<g1, 256, GEMM_SMEM>>>(
        (const __nv_bfloat16*)qh, (const __nv_bfloat16*)ql,
        (const __nv_bfloat16*)qh, (const __nv_bfloat16*)ql,
        attn, D, D, L, D,
        (size_t)L * D, (size_t)L * D, (size_t)L * L);

    // 3) softmax (+ emit P hi/lo)
    softmax_kernel<<<B * L, 256>>>(attn);

    // 4) O = P @ Q -> out
    dim3 g2(D / 128, L / 128, B);
    gemm_tc_kernel<false><<<g2, 256, GEMM_SMEM>>>(
        (const __nv_bfloat16*)ph, (const __nv_bfloat16*)pl,
        (const __nv_bfloat16*)qth, (const __nv_bfloat16*)qtl,
        out, L, L, D, L,
        (size_t)L * L, (size_t)D * L, (size_t)L * D);
}

// round 4
// speedup vs baseline: 2.1538x; 1.2939x over previous
#include <cuda_runtime.h>
#include <cuda_bf16.h>
#include <cstdint>

#define B   32
#define L   1024
#define D   256
#define INV_TEMP (1.0f/16.0f)

// ---------------------------------------------------------------------------
// Scratch (static device arrays; runtime allocation is forbidden)
// ---------------------------------------------------------------------------
__device__ __nv_bfloat16 g_qh [B * L * D];
__device__ __nv_bfloat16 g_ql [B * L * D];
__device__ __nv_bfloat16 g_qth[B * D * L];
__device__ __nv_bfloat16 g_qtl[B * D * L];
__device__ __nv_bfloat16 g_ph [B * L * L];
__device__ __nv_bfloat16 g_pl [B * L * L];

__device__ __forceinline__ float neg_inf() { return __int_as_float(0xff800000); }

__device__ __forceinline__ uint32_t smem_to_u32(const void* p) {
    uint32_t a;
    asm("{ .reg .u64 t; cvta.to.shared.u64 t, %1; cvt.u32.u64 %0, t; }" : "=r"(a) : "l"(p));
    return a;
}

#define SWZ(x) ((x) ^ (((x) >> 3) & 0x70))

__device__ __forceinline__ void ldsm_x4(uint32_t& r0, uint32_t& r1, uint32_t& r2, uint32_t& r3,
                                        uint32_t addr) {
    asm volatile("ldmatrix.sync.aligned.m8n8.x4.shared.b16 {%0,%1,%2,%3}, [%4];"
                 : "=r"(r0), "=r"(r1), "=r"(r2), "=r"(r3) : "r"(addr));
}

__device__ __forceinline__ void mma_bf16(float& c0, float& c1, float& c2, float& c3,
                                         uint32_t a0, uint32_t a1, uint32_t a2, uint32_t a3,
                                         uint32_t b0, uint32_t b1) {
    asm volatile("mma.sync.aligned.m16n8k16.row.col.f32.bf16.bf16.f32 "
                 "{%0,%1,%2,%3}, {%4,%5,%6,%7}, {%8,%9}, {%0,%1,%2,%3};"
                 : "+f"(c0), "+f"(c1), "+f"(c2), "+f"(c3)
                 : "r"(a0), "r"(a1), "r"(a2), "r"(a3), "r"(b0), "r"(b1));
}

#define CP_ASYNC_16(dst, src) \
    asm volatile("cp.async.cg.shared.global [%0], [%1], 16;" :: "r"(dst), "l"(src))
#define CP_ASYNC_COMMIT() asm volatile("cp.async.commit_group;" ::: "memory")
#define CP_ASYNC_WAIT(n)  asm volatile("cp.async.wait_group %0;" :: "n"(n) : "memory")

// ---------------------------------------------------------------------------
// Kernel A: split q -> bf16 hi/lo + transposed hi/lo copies.
// ---------------------------------------------------------------------------
__global__ void __launch_bounds__(256) split_q_kernel(const float* __restrict__ q) {
    const int b  = blockIdx.z;
    const int d0 = blockIdx.x * 32;
    const int l0 = blockIdx.y * 32;
    const float* Q = q + (size_t)b * L * D;
    __shared__ float t[32][33];
    const int tx = threadIdx.x, ty = threadIdx.y;

    #pragma unroll
    for (int i = 0; i < 4; i++) {
        const int r = ty + i * 8;
        const float v = Q[(size_t)(l0 + r) * D + d0 + tx];
        t[r][tx] = v;
        __nv_bfloat16 h  = __float2bfloat16(v);
        __nv_bfloat16 lo = __float2bfloat16(v - __bfloat162float(h));
        const size_t idx = (size_t)b * L * D + (size_t)(l0 + r) * D + d0 + tx;
        g_qh[idx] = h;
        g_ql[idx] = lo;
    }
    __syncthreads();
    #pragma unroll
    for (int i = 0; i < 4; i++) {
        const int r = ty + i * 8;
        const float v = t[tx][r];
        __nv_bfloat16 h  = __float2bfloat16(v);
        __nv_bfloat16 lo = __float2bfloat16(v - __bfloat162float(h));
        const size_t idx = (size_t)b * D * L + (size_t)(d0 + r) * L + l0 + tx;
        g_qth[idx] = h;
        g_qtl[idx] = lo;
    }
}

// ---------------------------------------------------------------------------
// mma.sync split-bf16 GEMM, cp.async double-buffered.
// CTA tile 128x128, 8 warps (4x2), K chunk 64.
// smem: 2 stages x [AH, AL, BH, BL] x 16KB = 128KB.
// ---------------------------------------------------------------------------
#define TILE_BYTES 16384
#define STAGE_BYTES (4 * TILE_BYTES)
#define GEMM_SMEM (2 * STAGE_BYTES)

__device__ __forceinline__ void issue_tile64(const __nv_bfloat16* __restrict__ src,
                                             int row0, int ld, int k0,
                                             uint32_t smem_tile, int tid) {
    #pragma unroll
    for (int i = 0; i < 4; i++) {
        const int chunk = tid + i * 256;
        const int row = chunk >> 3;
        const int c16 = chunk & 7;
        const __nv_bfloat16* g = src + (size_t)(row0 + row) * ld + k0 + c16 * 8;
        CP_ASYNC_16(smem_tile + SWZ((uint32_t)(row * 128 + c16 * 16)), g);
    }
}

template <bool MASK>
__global__ void __launch_bounds__(256)
gemm_tc_kernel(const __nv_bfloat16* __restrict__ Ah, const __nv_bfloat16* __restrict__ Al,
               const __nv_bfloat16* __restrict__ Bh, const __nv_bfloat16* __restrict__ Bl,
               float* __restrict__ C,
               int lda, int ldb, int ldc, int Ktot,
               size_t sA, size_t sB, size_t sC) {
    extern __shared__ char smem[];
    const uint32_t sb = smem_to_u32(smem);
    const int tid = threadIdx.x, wid = tid >> 5, lid = tid & 31;
    const int b  = blockIdx.z;
    const int m0 = blockIdx.y * 128;
    const int n0 = blockIdx.x * 128;

    const __nv_bfloat16* pAh = Ah + (size_t)b * sA;
    const __nv_bfloat16* pAl = Al + (size_t)b * sA;
    const __nv_bfloat16* pBh = Bh + (size_t)b * sB;
    const __nv_bfloat16* pBl = Bl + (size_t)b * sB;

    const int wm = wid & 3;
    const int wn = wid >> 2;
    const int rowbase = wm * 32;
    const int colbase = wn * 64;

    const int lrow = lid & 15;
    const uint32_t lkoff = (uint32_t)((lid >> 4) * 16);

    float acc[2][8][4];
    #pragma unroll
    for (int mt = 0; mt < 2; mt++)
        #pragma unroll
        for (int nt = 0; nt < 8; nt++)
            #pragma unroll
            for (int r = 0; r < 4; r++) acc[mt][nt][r] = 0.0f;

    const int nch = Ktot >> 6;

    // Prologue: issue chunk 0 into stage 0.
    {
        const uint32_t st = sb;
        issue_tile64(pAh, m0, lda, 0, st + 0 * TILE_BYTES, tid);
        issue_tile64(pAl, m0, lda, 0, st + 1 * TILE_BYTES, tid);
        issue_tile64(pBh, n0, ldb, 0, st + 2 * TILE_BYTES, tid);
        issue_tile64(pBl, n0, ldb, 0, st + 3 * TILE_BYTES, tid);
        CP_ASYNC_COMMIT();
    }

    for (int c = 0; c < nch; c++) {
        // Issue next chunk into the other stage, then wait for current.
        if (c + 1 < nch) {
            const int k1 = (c + 1) << 6;
            const uint32_t st = sb + (uint32_t)((c + 1) & 1) * STAGE_BYTES;
            issue_tile64(pAh, m0, lda, k1, st + 0 * TILE_BYTES, tid);
            issue_tile64(pAl, m0, lda, k1, st + 1 * TILE_BYTES, tid);
            issue_tile64(pBh, n0, ldb, k1, st + 2 * TILE_BYTES, tid);
            issue_tile64(pBl, n0, ldb, k1, st + 3 * TILE_BYTES, tid);
            CP_ASYNC_COMMIT();
            CP_ASYNC_WAIT(1);
        } else {
            CP_ASYNC_WAIT(0);
        }
        __syncthreads();

        const uint32_t st  = sb + (uint32_t)(c & 1) * STAGE_BYTES;
        const uint32_t aH = st + 0 * TILE_BYTES;
        const uint32_t aL = st + 1 * TILE_BYTES;
        const uint32_t bH = st + 2 * TILE_BYTES;
        const uint32_t bL = st + 3 * TILE_BYTES;

        #pragma unroll
        for (int ks = 0; ks < 4; ks++) {
            const uint32_t kb = (uint32_t)(ks * 32) + lkoff;
            uint32_t ah[2][4], al[2][4];
            #pragma unroll
            for (int mt = 0; mt < 2; mt++) {
                const uint32_t boff = (uint32_t)((rowbase + mt * 16 + lrow) * 128) + kb;
                ldsm_x4(ah[mt][0], ah[mt][1], ah[mt][2], ah[mt][3], aH + SWZ(boff));
                ldsm_x4(al[mt][0], al[mt][1], al[mt][2], al[mt][3], aL + SWZ(boff));
            }
            #pragma unroll
            for (int np = 0; np < 4; np++) {
                const uint32_t boff = (uint32_t)((colbase + np * 16 + lrow) * 128) + kb;
                uint32_t bh[4], bl[4];
                ldsm_x4(bh[0], bh[1], bh[2], bh[3], bH + SWZ(boff));
                ldsm_x4(bl[0], bl[1], bl[2], bl[3], bL + SWZ(boff));
                #pragma unroll
                for (int mt = 0; mt < 2; mt++) {
                    float* c0 = acc[mt][np * 2 + 0];
                    float* c1 = acc[mt][np * 2 + 1];
                    // Ah @ Bh
                    mma_bf16(c0[0], c0[1], c0[2], c0[3],
                             ah[mt][0], ah[mt][1], ah[mt][2], ah[mt][3], bh[0], bh[2]);
                    mma_bf16(c1[0], c1[1], c1[2], c1[3],
                             ah[mt][0], ah[mt][1], ah[mt][2], ah[mt][3], bh[1], bh[3]);
                    // Ah @ Bl
                    mma_bf16(c0[0], c0[1], c0[2], c0[3],
                             ah[mt][0], ah[mt][1], ah[mt][2], ah[mt][3], bl[0], bl[2]);
                    mma_bf16(c1[0], c1[1], c1[2], c1[3],
                             ah[mt][0], ah[mt][1], ah[mt][2], ah[mt][3], bl[1], bl[3]);
                    // Al @ Bh
                    mma_bf16(c0[0], c0[1], c0[2], c0[3],
                             al[mt][0], al[mt][1], al[mt][2], al[mt][3], bh[0], bh[2]);
                    mma_bf16(c1[0], c1[1], c1[2], c1[3],
                             al[mt][0], al[mt][1], al[mt][2], al[mt][3], bh[1], bh[3]);
                }
            }
        }
        __syncthreads();   // all warps done reading this stage before it is refilled
    }

    // Epilogue
    float* pC = C + (size_t)b * sC;
    const int trow = lid >> 2;
    const int tcol = (lid & 3) * 2;
    #pragma unroll
    for (int mt = 0; mt < 2; mt++) {
        #pragma unroll
        for (int nt = 0; nt < 8; nt++) {
            const int row = m0 + rowbase + mt * 16 + trow;
            const int col = n0 + colbase + nt * 8 + tcol;
            float v0 = acc[mt][nt][0], v1 = acc[mt][nt][1];
            float v2 = acc[mt][nt][2], v3 = acc[mt][nt][3];
            if (MASK) {
                v0 = (v0 == 0.0f) ? neg_inf() : v0 * INV_TEMP;
                v1 = (v1 == 0.0f) ? neg_inf() : v1 * INV_TEMP;
                v2 = (v2 == 0.0f) ? neg_inf() : v2 * INV_TEMP;
                v3 = (v3 == 0.0f) ? neg_inf() : v3 * INV_TEMP;
            }
            *(float2*)(pC + (size_t)row * ldc + col)       = make_float2(v0, v1);
            *(float2*)(pC + (size_t)(row + 8) * ldc + col) = make_float2(v2, v3);
        }
    }
}

// ---------------------------------------------------------------------------
// Kernel C: rowwise softmax in-place; emits P hi/lo bf16.
// ---------------------------------------------------------------------------
__global__ void __launch_bounds__(256) softmax_kernel(float* __restrict__ attn) {
    const size_t row = blockIdx.x;
    float* p = attn + row * L;
    __nv_bfloat16* ph = g_ph + row * L;
    __nv_bfloat16* pl = g_pl + row * L;
    const int tid = threadIdx.x;

    float4 v = ((const float4*)p)[tid];
    float m = fmaxf(fmaxf(v.x, v.y), fmaxf(v.z, v.w));
    #pragma unroll
    for (int o = 16; o > 0; o >>= 1) m = fmaxf(m, __shfl_xor_sync(0xffffffffu, m, o));

    __shared__ float smem[8];
    __shared__ float stat;
    const int wid = tid >> 5, lid = tid & 31;
    if (lid == 0) smem[wid] = m;
    __syncthreads();
    if (tid == 0) {
        float mm = smem[0];
        #pragma unroll
        for (int i = 1; i < 8; i++) mm = fmaxf(mm, smem[i]);
        stat = mm;
    }
    __syncthreads();
    const float rmax = stat;

    if (rmax == neg_inf()) {
        ((float4*)p)[tid] = make_float4(0.f, 0.f, 0.f, 0.f);
        const uint2 z = make_uint2(0u, 0u);
        ((uint2*)ph)[tid] = z;
        ((uint2*)pl)[tid] = z;
        return;
    }

    float4 e;
    e.x = __expf(v.x - rmax); e.y = __expf(v.y - rmax);
    e.z = __expf(v.z - rmax); e.w = __expf(v.w - rmax);
    float s = (e.x + e.y) + (e.z + e.w);
    #pragma unroll
    for (int o = 16; o > 0; o >>= 1) s += __shfl_xor_sync(0xffffffffu, s, o);
    if (lid == 0) smem[wid] = s;
    __syncthreads();
    if (tid == 0) {
        float ss = smem[0];
        #pragma unroll
        for (int i = 1; i < 8; i++) ss += smem[i];
        stat = 1.0f / ss;
    }
    __syncthreads();
    const float inv = stat;
    e.x *= inv; e.y *= inv; e.z *= inv; e.w *= inv;
    ((float4*)p)[tid] = e;

    __nv_bfloat16 h0 = __float2bfloat16(e.x), h1 = __float2bfloat16(e.y);
    __nv_bfloat16 h2 = __float2bfloat16(e.z), h3 = __float2bfloat16(e.w);
    __nv_bfloat16 l0 = __float2bfloat16(e.x - __bfloat162float(h0));
    __nv_bfloat16 l1 = __float2bfloat16(e.y - __bfloat162float(h1));
    __nv_bfloat16 l2 = __float2bfloat16(e.z - __bfloat162float(h2));
    __nv_bfloat16 l3 = __float2bfloat16(e.w - __bfloat162float(h3));
    __nv_bfloat162 hp0, hp1, lp0, lp1;
    hp0.x = h0; hp0.y = h1; hp1.x = h2; hp1.y = h3;
    lp0.x = l0; lp0.y = l1; lp1.x = l2; lp1.y = l3;
    ((__nv_bfloat162*)ph)[tid * 2]     = hp0;
    ((__nv_bfloat162*)ph)[tid * 2 + 1] = hp1;
    ((__nv_bfloat162*)pl)[tid * 2]     = lp0;
    ((__nv_bfloat162*)pl)[tid * 2 + 1] = lp1;
}

// ---------------------------------------------------------------------------
// Launch
// ---------------------------------------------------------------------------
extern "C" void kernel_launch(void* const* d_in, const int* in_sizes, int n_in,
                              void* d_out, int out_size) {
    const float* q = (const float*)d_in[0];
    float* out  = (float*)d_out;
    float* attn = (float*)d_out + (size_t)B * L * D;

    void *qh, *ql, *qth, *qtl, *ph, *pl;
    cudaGetSymbolAddress(&qh,  g_qh);
    cudaGetSymbolAddress(&ql,  g_ql);
    cudaGetSymbolAddress(&qth, g_qth);
    cudaGetSymbolAddress(&qtl, g_qtl);
    cudaGetSymbolAddress(&ph,  g_ph);
    cudaGetSymbolAddress(&pl,  g_pl);

    cudaFuncSetAttribute(gemm_tc_kernel<true>,  cudaFuncAttributeMaxDynamicSharedMemorySize, GEMM_SMEM);
    cudaFuncSetAttribute(gemm_tc_kernel<false>, cudaFuncAttributeMaxDynamicSharedMemorySize, GEMM_SMEM);

    dim3 gs(D / 32, L / 32, B);
    split_q_kernel<<<gs, dim3(32, 8)>>>(q);

    dim3 g1(L / 128, L / 128, B);
    gemm_tc_kernel<true><<<g1, 256, GEMM_SMEM>>>(
        (const __nv_bfloat16*)qh, (const __nv_bfloat16*)ql,
        (const __nv_bfloat16*)qh, (const __nv_bfloat16*)ql,
        attn, D, D, L, D,
        (size_t)L * D, (size_t)L * D, (size_t)L * L);

    softmax_kernel<<<B * L, 256>>>(attn);

    dim3 g2(D / 128, L / 128, B);
    gemm_tc_kernel<false><<<g2, 256, GEMM_SMEM>>>(
        (const __nv_bfloat16*)ph, (const __nv_bfloat16*)pl,
        (const __nv_bfloat16*)qth, (const __nv_bfloat16*)qtl,
        out, L, L, D, L,
        (size_t)L * L, (size_t)D * L, (size_t)L * D);
}

// round 5
// speedup vs baseline: 2.1740x; 1.0094x over previous
#include <cuda_runtime.h>
#include <cuda_bf16.h>
#include <cstdint>

#define B   32
#define L   1024
#define D   256
#define INV_TEMP (1.0f/16.0f)

// ---------------------------------------------------------------------------
// Scratch (static device arrays; runtime allocation is forbidden)
// ---------------------------------------------------------------------------
__device__ __nv_bfloat16 g_qh [B * L * D];
__device__ __nv_bfloat16 g_ql [B * L * D];
__device__ __nv_bfloat16 g_qth[B * D * L];
__device__ __nv_bfloat16 g_qtl[B * D * L];
__device__ __nv_bfloat16 g_ph [B * L * L];
__device__ __nv_bfloat16 g_pl [B * L * L];

__device__ __forceinline__ float neg_inf() { return __int_as_float(0xff800000); }

__device__ __forceinline__ uint32_t smem_to_u32(const void* p) {
    uint32_t a;
    asm("{ .reg .u64 t; cvta.to.shared.u64 t, %1; cvt.u32.u64 %0, t; }" : "=r"(a) : "l"(p));
    return a;
}

#define SWZ(x) ((x) ^ (((x) >> 3) & 0x70))

__device__ __forceinline__ void ldsm_x4(uint32_t& r0, uint32_t& r1, uint32_t& r2, uint32_t& r3,
                                        uint32_t addr) {
    asm volatile("ldmatrix.sync.aligned.m8n8.x4.shared.b16 {%0,%1,%2,%3}, [%4];"
                 : "=r"(r0), "=r"(r1), "=r"(r2), "=r"(r3) : "r"(addr));
}

__device__ __forceinline__ void mma_bf16(float& c0, float& c1, float& c2, float& c3,
                                         uint32_t a0, uint32_t a1, uint32_t a2, uint32_t a3,
                                         uint32_t b0, uint32_t b1) {
    asm volatile("mma.sync.aligned.m16n8k16.row.col.f32.bf16.bf16.f32 "
                 "{%0,%1,%2,%3}, {%4,%5,%6,%7}, {%8,%9}, {%0,%1,%2,%3};"
                 : "+f"(c0), "+f"(c1), "+f"(c2), "+f"(c3)
                 : "r"(a0), "r"(a1), "r"(a2), "r"(a3), "r"(b0), "r"(b1));
}

#define CP_ASYNC_16(dst, src) \
    asm volatile("cp.async.cg.shared.global [%0], [%1], 16;" :: "r"(dst), "l"(src))
#define CP_ASYNC_COMMIT() asm volatile("cp.async.commit_group;" ::: "memory")
#define CP_ASYNC_WAIT(n)  asm volatile("cp.async.wait_group %0;" :: "n"(n) : "memory")

// ---------------------------------------------------------------------------
// Kernel A: split q -> bf16 hi/lo + transposed hi/lo copies.
// ---------------------------------------------------------------------------
__global__ void __launch_bounds__(256) split_q_kernel(const float* __restrict__ q) {
    const int b  = blockIdx.z;
    const int d0 = blockIdx.x * 32;
    const int l0 = blockIdx.y * 32;
    const float* Q = q + (size_t)b * L * D;
    __shared__ float t[32][33];
    const int tx = threadIdx.x, ty = threadIdx.y;

    #pragma unroll
    for (int i = 0; i < 4; i++) {
        const int r = ty + i * 8;
        const float v = Q[(size_t)(l0 + r) * D + d0 + tx];
        t[r][tx] = v;
        __nv_bfloat16 h  = __float2bfloat16(v);
        __nv_bfloat16 lo = __float2bfloat16(v - __bfloat162float(h));
        const size_t idx = (size_t)b * L * D + (size_t)(l0 + r) * D + d0 + tx;
        g_qh[idx] = h;
        g_ql[idx] = lo;
    }
    __syncthreads();
    #pragma unroll
    for (int i = 0; i < 4; i++) {
        const int r = ty + i * 8;
        const float v = t[tx][r];
        __nv_bfloat16 h  = __float2bfloat16(v);
        __nv_bfloat16 lo = __float2bfloat16(v - __bfloat162float(h));
        const size_t idx = (size_t)b * D * L + (size_t)(d0 + r) * L + l0 + tx;
        g_qth[idx] = h;
        g_qtl[idx] = lo;
    }
}

// ---------------------------------------------------------------------------
// mma.sync split-bf16 GEMM, cp.async double-buffered.
// CTA tile 128x256, 8 warps in 2x4 (warp tile 64x64), K chunk 64.
// smem: 2 stages x [AH 16K, AL 16K, BH 32K, BL 32K] = 192KB.
// ---------------------------------------------------------------------------
#define TILE_A_BYTES 16384
#define TILE_B_BYTES 32768
#define STAGE_BYTES (2 * TILE_A_BYTES + 2 * TILE_B_BYTES)   // 96KB
#define GEMM_SMEM (2 * STAGE_BYTES)                          // 192KB
#define OFF_AH 0
#define OFF_AL TILE_A_BYTES
#define OFF_BH (2 * TILE_A_BYTES)
#define OFF_BL (2 * TILE_A_BYTES + TILE_B_BYTES)

template <int ROWS>
__device__ __forceinline__ void issue_tile(const __nv_bfloat16* __restrict__ src,
                                           int row0, int ld, int k0,
                                           uint32_t smem_tile, int tid) {
    #pragma unroll
    for (int i = 0; i < (ROWS * 8) / 256; i++) {
        const int chunk = tid + i * 256;
        const int row = chunk >> 3;
        const int c16 = chunk & 7;
        const __nv_bfloat16* g = src + (size_t)(row0 + row) * ld + k0 + c16 * 8;
        CP_ASYNC_16(smem_tile + SWZ((uint32_t)(row * 128 + c16 * 16)), g);
    }
}

template <bool MASK>
__global__ void __launch_bounds__(256)
gemm_tc_kernel(const __nv_bfloat16* __restrict__ Ah, const __nv_bfloat16* __restrict__ Al,
               const __nv_bfloat16* __restrict__ Bh, const __nv_bfloat16* __restrict__ Bl,
               float* __restrict__ C,
               int lda, int ldb, int ldc, int Ktot,
               size_t sA, size_t sB, size_t sC) {
    extern __shared__ char smem[];
    const uint32_t sb = smem_to_u32(smem);
    const int tid = threadIdx.x, wid = tid >> 5, lid = tid & 31;
    const int b  = blockIdx.z;
    const int m0 = blockIdx.y * 128;
    const int n0 = blockIdx.x * 256;

    const __nv_bfloat16* pAh = Ah + (size_t)b * sA;
    const __nv_bfloat16* pAl = Al + (size_t)b * sA;
    const __nv_bfloat16* pBh = Bh + (size_t)b * sB;
    const __nv_bfloat16* pBl = Bl + (size_t)b * sB;

    const int rowbase = (wid & 1) * 64;     // warp tile 64x64, 2x4 warp grid
    const int colbase = (wid >> 1) * 64;

    const int lrow = lid & 15;
    const uint32_t lkoff = (uint32_t)((lid >> 4) * 16);

    float acc[4][8][4];
    #pragma unroll
    for (int mt = 0; mt < 4; mt++)
        #pragma unroll
        for (int nt = 0; nt < 8; nt++)
            #pragma unroll
            for (int r = 0; r < 4; r++) acc[mt][nt][r] = 0.0f;

    const int nch = Ktot >> 6;

    // Prologue: chunk 0 -> stage 0
    {
        const uint32_t st = sb;
        issue_tile<128>(pAh, m0, lda, 0, st + OFF_AH, tid);
        issue_tile<128>(pAl, m0, lda, 0, st + OFF_AL, tid);
        issue_tile<256>(pBh, n0, ldb, 0, st + OFF_BH, tid);
        issue_tile<256>(pBl, n0, ldb, 0, st + OFF_BL, tid);
        CP_ASYNC_COMMIT();
    }

    for (int c = 0; c < nch; c++) {
        if (c + 1 < nch) {
            const int k1 = (c + 1) << 6;
            const uint32_t st = sb + (uint32_t)((c + 1) & 1) * STAGE_BYTES;
            issue_tile<128>(pAh, m0, lda, k1, st + OFF_AH, tid);
            issue_tile<128>(pAl, m0, lda, k1, st + OFF_AL, tid);
            issue_tile<256>(pBh, n0, ldb, k1, st + OFF_BH, tid);
            issue_tile<256>(pBl, n0, ldb, k1, st + OFF_BL, tid);
            CP_ASYNC_COMMIT();
            CP_ASYNC_WAIT(1);
        } else {
            CP_ASYNC_WAIT(0);
        }
        __syncthreads();

        const uint32_t st = sb + (uint32_t)(c & 1) * STAGE_BYTES;
        const uint32_t aH = st + OFF_AH;
        const uint32_t aL = st + OFF_AL;
        const uint32_t bH = st + OFF_BH;
        const uint32_t bL = st + OFF_BL;

        #pragma unroll
        for (int ks = 0; ks < 4; ks++) {
            const uint32_t kb = (uint32_t)(ks * 32) + lkoff;
            uint32_t ah[4][4], al[4][4];
            #pragma unroll
            for (int mt = 0; mt < 4; mt++) {
                const uint32_t boff = (uint32_t)((rowbase + mt * 16 + lrow) * 128) + kb;
                ldsm_x4(ah[mt][0], ah[mt][1], ah[mt][2], ah[mt][3], aH + SWZ(boff));
                ldsm_x4(al[mt][0], al[mt][1], al[mt][2], al[mt][3], aL + SWZ(boff));
            }
            #pragma unroll
            for (int np = 0; np < 4; np++) {
                const uint32_t boff = (uint32_t)((colbase + np * 16 + lrow) * 128) + kb;
                uint32_t bh[4], bl[4];
                ldsm_x4(bh[0], bh[1], bh[2], bh[3], bH + SWZ(boff));
                ldsm_x4(bl[0], bl[1], bl[2], bl[3], bL + SWZ(boff));
                #pragma unroll
                for (int mt = 0; mt < 4; mt++) {
                    float* c0 = acc[mt][np * 2 + 0];
                    float* c1 = acc[mt][np * 2 + 1];
                    mma_bf16(c0[0], c0[1], c0[2], c0[3],
                             ah[mt][0], ah[mt][1], ah[mt][2], ah[mt][3], bh[0], bh[2]);
                    mma_bf16(c1[0], c1[1], c1[2], c1[3],
                             ah[mt][0], ah[mt][1], ah[mt][2], ah[mt][3], bh[1], bh[3]);
                    mma_bf16(c0[0], c0[1], c0[2], c0[3],
                             ah[mt][0], ah[mt][1], ah[mt][2], ah[mt][3], bl[0], bl[2]);
                    mma_bf16(c1[0], c1[1], c1[2], c1[3],
                             ah[mt][0], ah[mt][1], ah[mt][2], ah[mt][3], bl[1], bl[3]);
                    mma_bf16(c0[0], c0[1], c0[2], c0[3],
                             al[mt][0], al[mt][1], al[mt][2], al[mt][3], bh[0], bh[2]);
                    mma_bf16(c1[0], c1[1], c1[2], c1[3],
                             al[mt][0], al[mt][1], al[mt][2], al[mt][3], bh[1], bh[3]);
                }
            }
        }
        __syncthreads();
    }

    // Epilogue
    float* pC = C + (size_t)b * sC;
    const int trow = lid >> 2;
    const int tcol = (lid & 3) * 2;
    #pragma unroll
    for (int mt = 0; mt < 4; mt++) {
        #pragma unroll
        for (int nt = 0; nt < 8; nt++) {
            const int row = m0 + rowbase + mt * 16 + trow;
            const int col = n0 + colbase + nt * 8 + tcol;
            float v0 = acc[mt][nt][0], v1 = acc[mt][nt][1];
            float v2 = acc[mt][nt][2], v3 = acc[mt][nt][3];
            if (MASK) {
                v0 = (v0 == 0.0f) ? neg_inf() : v0 * INV_TEMP;
                v1 = (v1 == 0.0f) ? neg_inf() : v1 * INV_TEMP;
                v2 = (v2 == 0.0f) ? neg_inf() : v2 * INV_TEMP;
                v3 = (v3 == 0.0f) ? neg_inf() : v3 * INV_TEMP;
            }
            *(float2*)(pC + (size_t)row * ldc + col)       = make_float2(v0, v1);
            *(float2*)(pC + (size_t)(row + 8) * ldc + col) = make_float2(v2, v3);
        }
    }
}

// ---------------------------------------------------------------------------
// Kernel C: rowwise softmax in-place; emits P hi/lo bf16.
// ---------------------------------------------------------------------------
__global__ void __launch_bounds__(256) softmax_kernel(float* __restrict__ attn) {
    const size_t row = blockIdx.x;
    float* p = attn + row * L;
    __nv_bfloat16* ph = g_ph + row * L;
    __nv_bfloat16* pl = g_pl + row * L;
    const int tid = threadIdx.x;

    float4 v = ((const float4*)p)[tid];
    float m = fmaxf(fmaxf(v.x, v.y), fmaxf(v.z, v.w));
    #pragma unroll
    for (int o = 16; o > 0; o >>= 1) m = fmaxf(m, __shfl_xor_sync(0xffffffffu, m, o));

    __shared__ float smem[8];
    __shared__ float stat;
    const int wid = tid >> 5, lid = tid & 31;
    if (lid == 0) smem[wid] = m;
    __syncthreads();
    if (tid == 0) {
        float mm = smem[0];
        #pragma unroll
        for (int i = 1; i < 8; i++) mm = fmaxf(mm, smem[i]);
        stat = mm;
    }
    __syncthreads();
    const float rmax = stat;

    if (rmax == neg_inf()) {
        ((float4*)p)[tid] = make_float4(0.f, 0.f, 0.f, 0.f);
        const uint2 z = make_uint2(0u, 0u);
        ((uint2*)ph)[tid] = z;
        ((uint2*)pl)[tid] = z;
        return;
    }

    float4 e;
    e.x = __expf(v.x - rmax); e.y = __expf(v.y - rmax);
    e.z = __expf(v.z - rmax); e.w = __expf(v.w - rmax);
    float s = (e.x + e.y) + (e.z + e.w);
    #pragma unroll
    for (int o = 16; o > 0; o >>= 1) s += __shfl_xor_sync(0xffffffffu, s, o);
    if (lid == 0) smem[wid] = s;
    __syncthreads();
    if (tid == 0) {
        float ss = smem[0];
        #pragma unroll
        for (int i = 1; i < 8; i++) ss += smem[i];
        stat = 1.0f / ss;
    }
    __syncthreads();
    const float inv = stat;
    e.x *= inv; e.y *= inv; e.z *= inv; e.w *= inv;
    ((float4*)p)[tid] = e;

    __nv_bfloat16 h0 = __float2bfloat16(e.x), h1 = __float2bfloat16(e.y);
    __nv_bfloat16 h2 = __float2bfloat16(e.z), h3 = __float2bfloat16(e.w);
    __nv_bfloat16 l0 = __float2bfloat16(e.x - __bfloat162float(h0));
    __nv_bfloat16 l1 = __float2bfloat16(e.y - __bfloat162float(h1));
    __nv_bfloat16 l2 = __float2bfloat16(e.z - __bfloat162float(h2));
    __nv_bfloat16 l3 = __float2bfloat16(e.w - __bfloat162float(h3));
    __nv_bfloat162 hp0, hp1, lp0, lp1;
    hp0.x = h0; hp0.y = h1; hp1.x = h2; hp1.y = h3;
    lp0.x = l0; lp0.y = l1; lp1.x = l2; lp1.y = l3;
    ((__nv_bfloat162*)ph)[tid * 2]     = hp0;
    ((__nv_bfloat162*)ph)[tid * 2 + 1] = hp1;
    ((__nv_bfloat162*)pl)[tid * 2]     = lp0;
    ((__nv_bfloat162*)pl)[tid * 2 + 1] = lp1;
}

// ---------------------------------------------------------------------------
// Launch
// ---------------------------------------------------------------------------
extern "C" void kernel_launch(void* const* d_in, const int* in_sizes, int n_in,
                              void* d_out, int out_size) {
    const float* q = (const float*)d_in[0];
    float* out  = (float*)d_out;
    float* attn = (float*)d_out + (size_t)B * L * D;

    void *qh, *ql, *qth, *qtl, *ph, *pl;
    cudaGetSymbolAddress(&qh,  g_qh);
    cudaGetSymbolAddress(&ql,  g_ql);
    cudaGetSymbolAddress(&qth, g_qth);
    cudaGetSymbolAddress(&qtl, g_qtl);
    cudaGetSymbolAddress(&ph,  g_ph);
    cudaGetSymbolAddress(&pl,  g_pl);

    cudaFuncSetAttribute(gemm_tc_kernel<true>,  cudaFuncAttributeMaxDynamicSharedMemorySize, GEMM_SMEM);
    cudaFuncSetAttribute(gemm_tc_kernel<false>, cudaFuncAttributeMaxDynamicSharedMemorySize, GEMM_SMEM);

    dim3 gs(D / 32, L / 32, B);
    split_q_kernel<<<gs, dim3(32, 8)>>>(q);

    // GEMM1: C 1024x1024, CTA 128x256
    dim3 g1(L / 256, L / 128, B);
    gemm_tc_kernel<true><<<g1, 256, GEMM_SMEM>>>(
        (const __nv_bfloat16*)qh, (const __nv_bfloat16*)ql,
        (const __nv_bfloat16*)qh, (const __nv_bfloat16*)ql,
        attn, D, D, L, D,
        (size_t)L * D, (size_t)L * D, (size_t)L * L);

    softmax_kernel<<<B * L, 256>>>(attn);

    // GEMM2: C 1024x256, CTA 128x256
    dim3 g2(D / 256, L / 128, B);
    gemm_tc_kernel<false><<<g2, 256, GEMM_SMEM>>>(
        (const __nv_bfloat16*)ph, (const __nv_bfloat16*)pl,
        (const __nv_bfloat16*)qth, (const __nv_bfloat16*)qtl,
        out, L, L, D, L,
        (size_t)L * L, (size_t)D * L, (size_t)L * D);
}

// round 6
// speedup vs baseline: 2.4406x; 1.1227x over previous
#include <cuda_runtime.h>
#include <cuda_bf16.h>
#include <cstdint>

#define B   32
#define L   1024
#define D   256
#define INV_TEMP (1.0f/16.0f)

// ---------------------------------------------------------------------------
// Scratch
// ---------------------------------------------------------------------------
__device__ __nv_bfloat16 g_qh [B * L * D];
__device__ __nv_bfloat16 g_ql [B * L * D];
__device__ __nv_bfloat16 g_qth[B * D * L];
__device__ __nv_bfloat16 g_qtl[B * D * L];
__device__ __nv_bfloat16 g_ph [B * L * L];
__device__ __nv_bfloat16 g_pl [B * L * L];

// upper-triangle block pair decode (8x8 blocks -> 36 pairs)
__constant__ uint8_t c_bi[36] = {0,0,0,0,0,0,0,0, 1,1,1,1,1,1,1, 2,2,2,2,2,2,
                                 3,3,3,3,3, 4,4,4,4, 5,5,5, 6,6, 7};
__constant__ uint8_t c_bj[36] = {0,1,2,3,4,5,6,7, 1,2,3,4,5,6,7, 2,3,4,5,6,7,
                                 3,4,5,6,7, 4,5,6,7, 5,6,7, 6,7, 7};

__device__ __forceinline__ float neg_inf() { return __int_as_float(0xff800000); }

__device__ __forceinline__ uint32_t smem_to_u32(const void* p) {
    uint32_t a;
    asm("{ .reg .u64 t; cvta.to.shared.u64 t, %1; cvt.u32.u64 %0, t; }" : "=r"(a) : "l"(p));
    return a;
}

#define SWZ(x) ((x) ^ (((x) >> 3) & 0x70))

__device__ __forceinline__ void ldsm_x4(uint32_t& r0, uint32_t& r1, uint32_t& r2, uint32_t& r3,
                                        uint32_t addr) {
    asm volatile("ldmatrix.sync.aligned.m8n8.x4.shared.b16 {%0,%1,%2,%3}, [%4];"
                 : "=r"(r0), "=r"(r1), "=r"(r2), "=r"(r3) : "r"(addr));
}

__device__ __forceinline__ void mma_bf16(float& c0, float& c1, float& c2, float& c3,
                                         uint32_t a0, uint32_t a1, uint32_t a2, uint32_t a3,
                                         uint32_t b0, uint32_t b1) {
    asm volatile("mma.sync.aligned.m16n8k16.row.col.f32.bf16.bf16.f32 "
                 "{%0,%1,%2,%3}, {%4,%5,%6,%7}, {%8,%9}, {%0,%1,%2,%3};"
                 : "+f"(c0), "+f"(c1), "+f"(c2), "+f"(c3)
                 : "r"(a0), "r"(a1), "r"(a2), "r"(a3), "r"(b0), "r"(b1));
}

#define CP_ASYNC_16(dst, src) \
    asm volatile("cp.async.cg.shared.global [%0], [%1], 16;" :: "r"(dst), "l"(src))
#define CP_ASYNC_COMMIT() asm volatile("cp.async.commit_group;" ::: "memory")
#define CP_ASYNC_WAIT(n)  asm volatile("cp.async.wait_group %0;" :: "n"(n) : "memory")

// ---------------------------------------------------------------------------
// Kernel A: split q -> bf16 hi/lo + transposed hi/lo copies.
// ---------------------------------------------------------------------------
__global__ void __launch_bounds__(256) split_q_kernel(const float* __restrict__ q) {
    const int b  = blockIdx.z;
    const int d0 = blockIdx.x * 32;
    const int l0 = blockIdx.y * 32;
    const float* Q = q + (size_t)b * L * D;
    __shared__ float t[32][33];
    const int tx = threadIdx.x, ty = threadIdx.y;

    #pragma unroll
    for (int i = 0; i < 4; i++) {
        const int r = ty + i * 8;
        const float v = Q[(size_t)(l0 + r) * D + d0 + tx];
        t[r][tx] = v;
        __nv_bfloat16 h  = __float2bfloat16(v);
        __nv_bfloat16 lo = __float2bfloat16(v - __bfloat162float(h));
        const size_t idx = (size_t)b * L * D + (size_t)(l0 + r) * D + d0 + tx;
        g_qh[idx] = h;
        g_ql[idx] = lo;
    }
    __syncthreads();
    #pragma unroll
    for (int i = 0; i < 4; i++) {
        const int r = ty + i * 8;
        const float v = t[tx][r];
        __nv_bfloat16 h  = __float2bfloat16(v);
        __nv_bfloat16 lo = __float2bfloat16(v - __bfloat162float(h));
        const size_t idx = (size_t)b * D * L + (size_t)(d0 + r) * L + l0 + tx;
        g_qth[idx] = h;
        g_qtl[idx] = lo;
    }
}

// ---------------------------------------------------------------------------
// Shared GEMM machinery: CTA 128x128, 8 warps (4x2), warp tile 32x64,
// K chunk 64, 2-stage cp.async. smem 2 x 64KB = 128KB.
// ---------------------------------------------------------------------------
#define TILE_BYTES 16384
#define STAGE_BYTES (4 * TILE_BYTES)
#define GEMM_SMEM (2 * STAGE_BYTES)

__device__ __forceinline__ void issue_tile64(const __nv_bfloat16* __restrict__ src,
                                             int row0, int ld, int k0,
                                             uint32_t smem_tile, int tid) {
    #pragma unroll
    for (int i = 0; i < 4; i++) {
        const int chunk = tid + i * 256;
        const int row = chunk >> 3;
        const int c16 = chunk & 7;
        const __nv_bfloat16* g = src + (size_t)(row0 + row) * ld + k0 + c16 * 8;
        CP_ASYNC_16(smem_tile + SWZ((uint32_t)(row * 128 + c16 * 16)), g);
    }
}

// Mainloop shared by both GEMM kernels. acc[2][8][4].
__device__ __forceinline__ void gemm_mainloop(
        const __nv_bfloat16* pAh, const __nv_bfloat16* pAl,
        const __nv_bfloat16* pBh, const __nv_bfloat16* pBl,
        int m0, int n0, int lda, int ldb, int Ktot,
        uint32_t sb, int tid, int rowbase, int colbase,
        int lrow, uint32_t lkoff, float acc[2][8][4]) {
    const int nch = Ktot >> 6;
    {
        const uint32_t st = sb;
        issue_tile64(pAh, m0, lda, 0, st + 0 * TILE_BYTES, tid);
        issue_tile64(pAl, m0, lda, 0, st + 1 * TILE_BYTES, tid);
        issue_tile64(pBh, n0, ldb, 0, st + 2 * TILE_BYTES, tid);
        issue_tile64(pBl, n0, ldb, 0, st + 3 * TILE_BYTES, tid);
        CP_ASYNC_COMMIT();
    }
    for (int c = 0; c < nch; c++) {
        if (c + 1 < nch) {
            const int k1 = (c + 1) << 6;
            const uint32_t st = sb + (uint32_t)((c + 1) & 1) * STAGE_BYTES;
            issue_tile64(pAh, m0, lda, k1, st + 0 * TILE_BYTES, tid);
            issue_tile64(pAl, m0, lda, k1, st + 1 * TILE_BYTES, tid);
            issue_tile64(pBh, n0, ldb, k1, st + 2 * TILE_BYTES, tid);
            issue_tile64(pBl, n0, ldb, k1, st + 3 * TILE_BYTES, tid);
            CP_ASYNC_COMMIT();
            CP_ASYNC_WAIT(1);
        } else {
            CP_ASYNC_WAIT(0);
        }
        __syncthreads();

        const uint32_t st = sb + (uint32_t)(c & 1) * STAGE_BYTES;
        const uint32_t aH = st + 0 * TILE_BYTES;
        const uint32_t aL = st + 1 * TILE_BYTES;
        const uint32_t bH = st + 2 * TILE_BYTES;
        const uint32_t bL = st + 3 * TILE_BYTES;

        #pragma unroll
        for (int ks = 0; ks < 4; ks++) {
            const uint32_t kb = (uint32_t)(ks * 32) + lkoff;
            uint32_t ah[2][4], al[2][4];
            #pragma unroll
            for (int mt = 0; mt < 2; mt++) {
                const uint32_t boff = (uint32_t)((rowbase + mt * 16 + lrow) * 128) + kb;
                ldsm_x4(ah[mt][0], ah[mt][1], ah[mt][2], ah[mt][3], aH + SWZ(boff));
                ldsm_x4(al[mt][0], al[mt][1], al[mt][2], al[mt][3], aL + SWZ(boff));
            }
            #pragma unroll
            for (int np = 0; np < 4; np++) {
                const uint32_t boff = (uint32_t)((colbase + np * 16 + lrow) * 128) + kb;
                uint32_t bh[4], bl[4];
                ldsm_x4(bh[0], bh[1], bh[2], bh[3], bH + SWZ(boff));
                ldsm_x4(bl[0], bl[1], bl[2], bl[3], bL + SWZ(boff));
                #pragma unroll
                for (int mt = 0; mt < 2; mt++) {
                    float* c0 = acc[mt][np * 2 + 0];
                    float* c1 = acc[mt][np * 2 + 1];
                    mma_bf16(c0[0], c0[1], c0[2], c0[3],
                             ah[mt][0], ah[mt][1], ah[mt][2], ah[mt][3], bh[0], bh[2]);
                    mma_bf16(c1[0], c1[1], c1[2], c1[3],
                             ah[mt][0], ah[mt][1], ah[mt][2], ah[mt][3], bh[1], bh[3]);
                    mma_bf16(c0[0], c0[1], c0[2], c0[3],
                             ah[mt][0], ah[mt][1], ah[mt][2], ah[mt][3], bl[0], bl[2]);
                    mma_bf16(c1[0], c1[1], c1[2], c1[3],
                             ah[mt][0], ah[mt][1], ah[mt][2], ah[mt][3], bl[1], bl[3]);
                    mma_bf16(c0[0], c0[1], c0[2], c0[3],
                             al[mt][0], al[mt][1], al[mt][2], al[mt][3], bh[0], bh[2]);
                    mma_bf16(c1[0], c1[1], c1[2], c1[3],
                             al[mt][0], al[mt][1], al[mt][2], al[mt][3], bh[1], bh[3]);
                }
            }
        }
        __syncthreads();
    }
}

// ---------------------------------------------------------------------------
// GEMM1 (symmetric): S = Q@Q^T, only block pairs bi<=bj; mask+scale epilogue;
// off-diagonal tiles also written transposed via smem staging.
// grid (36, 1, B)
// ---------------------------------------------------------------------------
__global__ void __launch_bounds__(256)
gemm_qqt_sym_kernel(const __nv_bfloat16* __restrict__ Qh, const __nv_bfloat16* __restrict__ Ql,
                    float* __restrict__ S) {
    extern __shared__ char smem[];
    const uint32_t sb = smem_to_u32(smem);
    const int tid = threadIdx.x, wid = tid >> 5, lid = tid & 31;
    const int b  = blockIdx.z;
    const int bi = c_bi[blockIdx.x];
    const int bj = c_bj[blockIdx.x];
    const int m0 = bi * 128;
    const int n0 = bj * 128;

    const __nv_bfloat16* pAh = Qh + (size_t)b * L * D;
    const __nv_bfloat16* pAl = Ql + (size_t)b * L * D;

    const int rowbase = (wid & 3) * 32;
    const int colbase = (wid >> 2) * 64;
    const int lrow = lid & 15;
    const uint32_t lkoff = (uint32_t)((lid >> 4) * 16);

    float acc[2][8][4];
    #pragma unroll
    for (int mt = 0; mt < 2; mt++)
        #pragma unroll
        for (int nt = 0; nt < 8; nt++)
            #pragma unroll
            for (int r = 0; r < 4; r++) acc[mt][nt][r] = 0.0f;

    gemm_mainloop(pAh, pAl, pAh, pAl, m0, n0, D, D, D,
                  sb, tid, rowbase, colbase, lrow, lkoff, acc);

    // mask + scale in place
    #pragma unroll
    for (int mt = 0; mt < 2; mt++)
        #pragma unroll
        for (int nt = 0; nt < 8; nt++)
            #pragma unroll
            for (int r = 0; r < 4; r++) {
                float v = acc[mt][nt][r];
                acc[mt][nt][r] = (v == 0.0f) ? neg_inf() : v * INV_TEMP;
            }

    float* pS = S + (size_t)b * L * L;
    const int trow = lid >> 2;
    const int tcol = (lid & 3) * 2;

    // direct tile write: S[m0+i][n0+j]
    #pragma unroll
    for (int mt = 0; mt < 2; mt++) {
        #pragma unroll
        for (int nt = 0; nt < 8; nt++) {
            const int row = m0 + rowbase + mt * 16 + trow;
            const int col = n0 + colbase + nt * 8 + tcol;
            *(float2*)(pS + (size_t)row * L + col) =
                make_float2(acc[mt][nt][0], acc[mt][nt][1]);
            *(float2*)(pS + (size_t)(row + 8) * L + col) =
                make_float2(acc[mt][nt][2], acc[mt][nt][3]);
        }
    }

    if (bi != bj) {
        // stage transpose: smemT[j][i] = T[i][j], pad 132 floats/row
        float* smemT = (float*)smem;
        __syncthreads();   // mainloop smem reads done in all warps
        #pragma unroll
        for (int mt = 0; mt < 2; mt++) {
            #pragma unroll
            for (int nt = 0; nt < 8; nt++) {
                const int i0 = rowbase + mt * 16 + trow;
                const int j0 = colbase + nt * 8 + tcol;
                smemT[(j0 + 0) * 132 + i0]     = acc[mt][nt][0];
                smemT[(j0 + 1) * 132 + i0]     = acc[mt][nt][1];
                smemT[(j0 + 0) * 132 + i0 + 8] = acc[mt][nt][2];
                smemT[(j0 + 1) * 132 + i0 + 8] = acc[mt][nt][3];
            }
        }
        __syncthreads();
        // transposed write: S[n0+j][m0+i] = T[i][j], coalesced float4
        const int j    = tid >> 1;          // 0..127
        const int half = (tid & 1) * 64;
        float* dst = pS + (size_t)(n0 + j) * L + m0 + half;
        const float* srcrow = smemT + j * 132 + half;
        #pragma unroll
        for (int u = 0; u < 16; u++) {
            *(float4*)(dst + u * 4) = *(const float4*)(srcrow + u * 4);
        }
    }
}

// ---------------------------------------------------------------------------
// GEMM2: O = P @ Q. grid (D/128, L/128, B)
// ---------------------------------------------------------------------------
__global__ void __launch_bounds__(256)
gemm_pv_kernel(const __nv_bfloat16* __restrict__ Ph, const __nv_bfloat16* __restrict__ Pl,
               const __nv_bfloat16* __restrict__ Bh, const __nv_bfloat16* __restrict__ Bl,
               float* __restrict__ O) {
    extern __shared__ char smem[];
    const uint32_t sb = smem_to_u32(smem);
    const int tid = threadIdx.x, wid = tid >> 5, lid = tid & 31;
    const int b  = blockIdx.z;
    const int m0 = blockIdx.y * 128;
    const int n0 = blockIdx.x * 128;

    const __nv_bfloat16* pAh = Ph + (size_t)b * L * L;
    const __nv_bfloat16* pAl = Pl + (size_t)b * L * L;
    const __nv_bfloat16* pBh = Bh + (size_t)b * D * L;
    const __nv_bfloat16* pBl = Bl + (size_t)b * D * L;

    const int rowbase = (wid & 3) * 32;
    const int colbase = (wid >> 2) * 64;
    const int lrow = lid & 15;
    const uint32_t lkoff = (uint32_t)((lid >> 4) * 16);

    float acc[2][8][4];
    #pragma unroll
    for (int mt = 0; mt < 2; mt++)
        #pragma unroll
        for (int nt = 0; nt < 8; nt++)
            #pragma unroll
            for (int r = 0; r < 4; r++) acc[mt][nt][r] = 0.0f;

    gemm_mainloop(pAh, pAl, pBh, pBl, m0, n0, L, L, L,
                  sb, tid, rowbase, colbase, lrow, lkoff, acc);

    float* pO = O + (size_t)b * L * D;
    const int trow = lid >> 2;
    const int tcol = (lid & 3) * 2;
    #pragma unroll
    for (int mt = 0; mt < 2; mt++) {
        #pragma unroll
        for (int nt = 0; nt < 8; nt++) {
            const int row = m0 + rowbase + mt * 16 + trow;
            const int col = n0 + colbase + nt * 8 + tcol;
            *(float2*)(pO + (size_t)row * D + col) =
                make_float2(acc[mt][nt][0], acc[mt][nt][1]);
            *(float2*)(pO + (size_t)(row + 8) * D + col) =
                make_float2(acc[mt][nt][2], acc[mt][nt][3]);
        }
    }
}

// ---------------------------------------------------------------------------
// softmax in-place; emits P hi/lo bf16.
// ---------------------------------------------------------------------------
__global__ void __launch_bounds__(256) softmax_kernel(float* __restrict__ attn) {
    const size_t row = blockIdx.x;
    float* p = attn + row * L;
    __nv_bfloat16* ph = g_ph + row * L;
    __nv_bfloat16* pl = g_pl + row * L;
    const int tid = threadIdx.x;

    float4 v = ((const float4*)p)[tid];
    float m = fmaxf(fmaxf(v.x, v.y), fmaxf(v.z, v.w));
    #pragma unroll
    for (int o = 16; o > 0; o >>= 1) m = fmaxf(m, __shfl_xor_sync(0xffffffffu, m, o));

    __shared__ float smem[8];
    __shared__ float stat;
    const int wid = tid >> 5, lid = tid & 31;
    if (lid == 0) smem[wid] = m;
    __syncthreads();
    if (tid == 0) {
        float mm = smem[0];
        #pragma unroll
        for (int i = 1; i < 8; i++) mm = fmaxf(mm, smem[i]);
        stat = mm;
    }
    __syncthreads();
    const float rmax = stat;

    if (rmax == neg_inf()) {
        ((float4*)p)[tid] = make_float4(0.f, 0.f, 0.f, 0.f);
        const uint2 z = make_uint2(0u, 0u);
        ((uint2*)ph)[tid] = z;
        ((uint2*)pl)[tid] = z;
        return;
    }

    float4 e;
    e.x = __expf(v.x - rmax); e.y = __expf(v.y - rmax);
    e.z = __expf(v.z - rmax); e.w = __expf(v.w - rmax);
    float s = (e.x + e.y) + (e.z + e.w);
    #pragma unroll
    for (int o = 16; o > 0; o >>= 1) s += __shfl_xor_sync(0xffffffffu, s, o);
    if (lid == 0) smem[wid] = s;
    __syncthreads();
    if (tid == 0) {
        float ss = smem[0];
        #pragma unroll
        for (int i = 1; i < 8; i++) ss += smem[i];
        stat = 1.0f / ss;
    }
    __syncthreads();
    const float inv = stat;
    e.x *= inv; e.y *= inv; e.z *= inv; e.w *= inv;
    ((float4*)p)[tid] = e;

    __nv_bfloat16 h0 = __float2bfloat16(e.x), h1 = __float2bfloat16(e.y);
    __nv_bfloat16 h2 = __float2bfloat16(e.z), h3 = __float2bfloat16(e.w);
    __nv_bfloat16 l0 = __float2bfloat16(e.x - __bfloat162float(h0));
    __nv_bfloat16 l1 = __float2bfloat16(e.y - __bfloat162float(h1));
    __nv_bfloat16 l2 = __float2bfloat16(e.z - __bfloat162float(h2));
    __nv_bfloat16 l3 = __float2bfloat16(e.w - __bfloat162float(h3));
    __nv_bfloat162 hp0, hp1, lp0, lp1;
    hp0.x = h0; hp0.y = h1; hp1.x = h2; hp1.y = h3;
    lp0.x = l0; lp0.y = l1; lp1.x = l2; lp1.y = l3;
    ((__nv_bfloat162*)ph)[tid * 2]     = hp0;
    ((__nv_bfloat162*)ph)[tid * 2 + 1] = hp1;
    ((__nv_bfloat162*)pl)[tid * 2]     = lp0;
    ((__nv_bfloat162*)pl)[tid * 2 + 1] = lp1;
}

// ---------------------------------------------------------------------------
// Launch
// ---------------------------------------------------------------------------
extern "C" void kernel_launch(void* const* d_in, const int* in_sizes, int n_in,
                              void* d_out, int out_size) {
    const float* q = (const float*)d_in[0];
    float* out  = (float*)d_out;
    float* attn = (float*)d_out + (size_t)B * L * D;

    void *qh, *ql, *qth, *qtl, *ph, *pl;
    cudaGetSymbolAddress(&qh,  g_qh);
    cudaGetSymbolAddress(&ql,  g_ql);
    cudaGetSymbolAddress(&qth, g_qth);
    cudaGetSymbolAddress(&qtl, g_qtl);
    cudaGetSymbolAddress(&ph,  g_ph);
    cudaGetSymbolAddress(&pl,  g_pl);

    cudaFuncSetAttribute(gemm_qqt_sym_kernel, cudaFuncAttributeMaxDynamicSharedMemorySize, GEMM_SMEM);
    cudaFuncSetAttribute(gemm_pv_kernel,      cudaFuncAttributeMaxDynamicSharedMemorySize, GEMM_SMEM);

    dim3 gs(D / 32, L / 32, B);
    split_q_kernel<<<gs, dim3(32, 8)>>>(q);

    // GEMM1 (symmetric): 36 block pairs per batch
    dim3 g1(36, 1, B);
    gemm_qqt_sym_kernel<<<g1, 256, GEMM_SMEM>>>(
        (const __nv_bfloat16*)qh, (const __nv_bfloat16*)ql, attn);

    softmax_kernel<<<B * L, 256>>>(attn);

    // GEMM2: O = P @ Q
    dim3 g2(D / 128, L / 128, B);
    gemm_pv_kernel<<<g2, 256, GEMM_SMEM>>>(
        (const __nv_bfloat16*)ph, (const __nv_bfloat16*)pl,
        (const __nv_bfloat16*)qth, (const __nv_bfloat16*)qtl, out);
}

// round 7
// speedup vs baseline: 2.4429x; 1.0009x over previous
#include <cuda_runtime.h>
#include <cuda_bf16.h>
#include <cstdint>

#define B   32
#define L   1024
#define D   256
#define INV_TEMP (1.0f/16.0f)

// ---------------------------------------------------------------------------
// Scratch
// ---------------------------------------------------------------------------
__device__ __nv_bfloat16 g_qh [B * L * D];
__device__ __nv_bfloat16 g_ql [B * L * D];
__device__ __nv_bfloat16 g_qth[B * D * L];
__device__ __nv_bfloat16 g_qtl[B * D * L];
__device__ __nv_bfloat16 g_ph [B * L * L];
__device__ __nv_bfloat16 g_pl [B * L * L];

// upper-triangle block pair decode (8x8 blocks -> 36 pairs)
__constant__ uint8_t c_bi[36] = {0,0,0,0,0,0,0,0, 1,1,1,1,1,1,1, 2,2,2,2,2,2,
                                 3,3,3,3,3, 4,4,4,4, 5,5,5, 6,6, 7};
__constant__ uint8_t c_bj[36] = {0,1,2,3,4,5,6,7, 1,2,3,4,5,6,7, 2,3,4,5,6,7,
                                 3,4,5,6,7, 4,5,6,7, 5,6,7, 6,7, 7};

__device__ __forceinline__ float neg_inf() { return __int_as_float(0xff800000); }

__device__ __forceinline__ uint32_t smem_to_u32(const void* p) {
    uint32_t a;
    asm("{ .reg .u64 t; cvta.to.shared.u64 t, %1; cvt.u32.u64 %0, t; }" : "=r"(a) : "l"(p));
    return a;
}

#define SWZ(x) ((x) ^ (((x) >> 3) & 0x70))

__device__ __forceinline__ void ldsm_x4(uint32_t& r0, uint32_t& r1, uint32_t& r2, uint32_t& r3,
                                        uint32_t addr) {
    asm volatile("ldmatrix.sync.aligned.m8n8.x4.shared.b16 {%0,%1,%2,%3}, [%4];"
                 : "=r"(r0), "=r"(r1), "=r"(r2), "=r"(r3) : "r"(addr));
}

__device__ __forceinline__ void mma_bf16(float& c0, float& c1, float& c2, float& c3,
                                         uint32_t a0, uint32_t a1, uint32_t a2, uint32_t a3,
                                         uint32_t b0, uint32_t b1) {
    asm volatile("mma.sync.aligned.m16n8k16.row.col.f32.bf16.bf16.f32 "
                 "{%0,%1,%2,%3}, {%4,%5,%6,%7}, {%8,%9}, {%0,%1,%2,%3};"
                 : "+f"(c0), "+f"(c1), "+f"(c2), "+f"(c3)
                 : "r"(a0), "r"(a1), "r"(a2), "r"(a3), "r"(b0), "r"(b1));
}

#define CP_ASYNC_16(dst, src) \
    asm volatile("cp.async.cg.shared.global [%0], [%1], 16;" :: "r"(dst), "l"(src))
#define CP_ASYNC_COMMIT() asm volatile("cp.async.commit_group;" ::: "memory")
#define CP_ASYNC_WAIT(n)  asm volatile("cp.async.wait_group %0;" :: "n"(n) : "memory")

// ---------------------------------------------------------------------------
// Kernel A: split q -> bf16 hi/lo + transposed hi/lo copies.
// ---------------------------------------------------------------------------
__global__ void __launch_bounds__(256) split_q_kernel(const float* __restrict__ q) {
    const int b  = blockIdx.z;
    const int d0 = blockIdx.x * 32;
    const int l0 = blockIdx.y * 32;
    const float* Q = q + (size_t)b * L * D;
    __shared__ float t[32][33];
    const int tx = threadIdx.x, ty = threadIdx.y;

    #pragma unroll
    for (int i = 0; i < 4; i++) {
        const int r = ty + i * 8;
        const float v = Q[(size_t)(l0 + r) * D + d0 + tx];
        t[r][tx] = v;
        __nv_bfloat16 h  = __float2bfloat16(v);
        __nv_bfloat16 lo = __float2bfloat16(v - __bfloat162float(h));
        const size_t idx = (size_t)b * L * D + (size_t)(l0 + r) * D + d0 + tx;
        g_qh[idx] = h;
        g_ql[idx] = lo;
    }
    __syncthreads();
    #pragma unroll
    for (int i = 0; i < 4; i++) {
        const int r = ty + i * 8;
        const float v = t[tx][r];
        __nv_bfloat16 h  = __float2bfloat16(v);
        __nv_bfloat16 lo = __float2bfloat16(v - __bfloat162float(h));
        const size_t idx = (size_t)b * D * L + (size_t)(d0 + r) * L + l0 + tx;
        g_qth[idx] = h;
        g_qtl[idx] = lo;
    }
}

// ---------------------------------------------------------------------------
// Shared GEMM machinery: CTA 128x128, 8 warps (4x2), warp tile 32x64,
// K chunk 64, 3-stage cp.async pipeline. smem 3 x 64KB = 192KB.
// One __syncthreads per chunk: after the readiness sync for chunk c, every
// warp has finished reading chunk c-1's buffer ((c-1)%3 == (c+2)%3), so the
// producer may immediately refill it.
// ---------------------------------------------------------------------------
#define TILE_BYTES 16384
#define STAGE_BYTES (4 * TILE_BYTES)
#define NSTAGE 3
#define GEMM_SMEM (NSTAGE * STAGE_BYTES)

__device__ __forceinline__ void issue_tile64(const __nv_bfloat16* __restrict__ src,
                                             int row0, int ld, int k0,
                                             uint32_t smem_tile, int tid) {
    #pragma unroll
    for (int i = 0; i < 4; i++) {
        const int chunk = tid + i * 256;
        const int row = chunk >> 3;
        const int c16 = chunk & 7;
        const __nv_bfloat16* g = src + (size_t)(row0 + row) * ld + k0 + c16 * 8;
        CP_ASYNC_16(smem_tile + SWZ((uint32_t)(row * 128 + c16 * 16)), g);
    }
}

__device__ __forceinline__ void issue_stage(
        const __nv_bfloat16* pAh, const __nv_bfloat16* pAl,
        const __nv_bfloat16* pBh, const __nv_bfloat16* pBl,
        int m0, int n0, int lda, int ldb, int k0,
        uint32_t st, int tid) {
    issue_tile64(pAh, m0, lda, k0, st + 0 * TILE_BYTES, tid);
    issue_tile64(pAl, m0, lda, k0, st + 1 * TILE_BYTES, tid);
    issue_tile64(pBh, n0, ldb, k0, st + 2 * TILE_BYTES, tid);
    issue_tile64(pBl, n0, ldb, k0, st + 3 * TILE_BYTES, tid);
    CP_ASYNC_COMMIT();
}

__device__ __forceinline__ void gemm_mainloop(
        const __nv_bfloat16* pAh, const __nv_bfloat16* pAl,
        const __nv_bfloat16* pBh, const __nv_bfloat16* pBl,
        int m0, int n0, int lda, int ldb, int Ktot,
        uint32_t sb, int tid, int rowbase, int colbase,
        int lrow, uint32_t lkoff, float acc[2][8][4]) {
    const int nch = Ktot >> 6;

    // Prologue: issue chunks 0 and 1.
    issue_stage(pAh, pAl, pBh, pBl, m0, n0, lda, ldb, 0, sb, tid);
    if (nch > 1)
        issue_stage(pAh, pAl, pBh, pBl, m0, n0, lda, ldb, 64, sb + STAGE_BYTES, tid);

    for (int c = 0; c < nch; c++) {
        if (c + 1 < nch) { CP_ASYNC_WAIT(1); } else { CP_ASYNC_WAIT(0); }
        __syncthreads();

        // Refill buffer (c+2)%3 (held chunk c-1, which all warps finished).
        if (c + 2 < nch) {
            issue_stage(pAh, pAl, pBh, pBl, m0, n0, lda, ldb, (c + 2) << 6,
                        sb + (uint32_t)((c + 2) % NSTAGE) * STAGE_BYTES, tid);
        }

        const uint32_t st = sb + (uint32_t)(c % NSTAGE) * STAGE_BYTES;
        const uint32_t aH = st + 0 * TILE_BYTES;
        const uint32_t aL = st + 1 * TILE_BYTES;
        const uint32_t bH = st + 2 * TILE_BYTES;
        const uint32_t bL = st + 3 * TILE_BYTES;

        #pragma unroll
        for (int ks = 0; ks < 4; ks++) {
            const uint32_t kb = (uint32_t)(ks * 32) + lkoff;
            uint32_t ah[2][4], al[2][4];
            #pragma unroll
            for (int mt = 0; mt < 2; mt++) {
                const uint32_t boff = (uint32_t)((rowbase + mt * 16 + lrow) * 128) + kb;
                ldsm_x4(ah[mt][0], ah[mt][1], ah[mt][2], ah[mt][3], aH + SWZ(boff));
                ldsm_x4(al[mt][0], al[mt][1], al[mt][2], al[mt][3], aL + SWZ(boff));
            }
            #pragma unroll
            for (int np = 0; np < 4; np++) {
                const uint32_t boff = (uint32_t)((colbase + np * 16 + lrow) * 128) + kb;
                uint32_t bh[4], bl[4];
                ldsm_x4(bh[0], bh[1], bh[2], bh[3], bH + SWZ(boff));
                ldsm_x4(bl[0], bl[1], bl[2], bl[3], bL + SWZ(boff));
                #pragma unroll
                for (int mt = 0; mt < 2; mt++) {
                    float* c0 = acc[mt][np * 2 + 0];
                    float* c1 = acc[mt][np * 2 + 1];
                    mma_bf16(c0[0], c0[1], c0[2], c0[3],
                             ah[mt][0], ah[mt][1], ah[mt][2], ah[mt][3], bh[0], bh[2]);
                    mma_bf16(c1[0], c1[1], c1[2], c1[3],
                             ah[mt][0], ah[mt][1], ah[mt][2], ah[mt][3], bh[1], bh[3]);
                    mma_bf16(c0[0], c0[1], c0[2], c0[3],
                             ah[mt][0], ah[mt][1], ah[mt][2], ah[mt][3], bl[0], bl[2]);
                    mma_bf16(c1[0], c1[1], c1[2], c1[3],
                             ah[mt][0], ah[mt][1], ah[mt][2], ah[mt][3], bl[1], bl[3]);
                    mma_bf16(c0[0], c0[1], c0[2], c0[3],
                             al[mt][0], al[mt][1], al[mt][2], al[mt][3], bh[0], bh[2]);
                    mma_bf16(c1[0], c1[1], c1[2], c1[3],
                             al[mt][0], al[mt][1], al[mt][2], al[mt][3], bh[1], bh[3]);
                }
            }
        }
    }
    __syncthreads();   // protect smem reuse by epilogue staging
}

// ---------------------------------------------------------------------------
// GEMM1 (symmetric): S = Q@Q^T, block pairs bi<=bj; mask+scale epilogue;
// off-diagonal tiles also written transposed. grid (36, 1, B)
// ---------------------------------------------------------------------------
__global__ void __launch_bounds__(256)
gemm_qqt_sym_kernel(const __nv_bfloat16* __restrict__ Qh, const __nv_bfloat16* __restrict__ Ql,
                    float* __restrict__ S) {
    extern __shared__ char smem[];
    const uint32_t sb = smem_to_u32(smem);
    const int tid = threadIdx.x, wid = tid >> 5, lid = tid & 31;
    const int b  = blockIdx.z;
    const int bi = c_bi[blockIdx.x];
    const int bj = c_bj[blockIdx.x];
    const int m0 = bi * 128;
    const int n0 = bj * 128;

    const __nv_bfloat16* pAh = Qh + (size_t)b * L * D;
    const __nv_bfloat16* pAl = Ql + (size_t)b * L * D;

    const int rowbase = (wid & 3) * 32;
    const int colbase = (wid >> 2) * 64;
    const int lrow = lid & 15;
    const uint32_t lkoff = (uint32_t)((lid >> 4) * 16);

    float acc[2][8][4];
    #pragma unroll
    for (int mt = 0; mt < 2; mt++)
        #pragma unroll
        for (int nt = 0; nt < 8; nt++)
            #pragma unroll
            for (int r = 0; r < 4; r++) acc[mt][nt][r] = 0.0f;

    gemm_mainloop(pAh, pAl, pAh, pAl, m0, n0, D, D, D,
                  sb, tid, rowbase, colbase, lrow, lkoff, acc);

    #pragma unroll
    for (int mt = 0; mt < 2; mt++)
        #pragma unroll
        for (int nt = 0; nt < 8; nt++)
            #pragma unroll
            for (int r = 0; r < 4; r++) {
                float v = acc[mt][nt][r];
                acc[mt][nt][r] = (v == 0.0f) ? neg_inf() : v * INV_TEMP;
            }

    float* pS = S + (size_t)b * L * L;
    const int trow = lid >> 2;
    const int tcol = (lid & 3) * 2;

    #pragma unroll
    for (int mt = 0; mt < 2; mt++) {
        #pragma unroll
        for (int nt = 0; nt < 8; nt++) {
            const int row = m0 + rowbase + mt * 16 + trow;
            const int col = n0 + colbase + nt * 8 + tcol;
            *(float2*)(pS + (size_t)row * L + col) =
                make_float2(acc[mt][nt][0], acc[mt][nt][1]);
            *(float2*)(pS + (size_t)(row + 8) * L + col) =
                make_float2(acc[mt][nt][2], acc[mt][nt][3]);
        }
    }

    if (bi != bj) {
        float* smemT = (float*)smem;
        #pragma unroll
        for (int mt = 0; mt < 2; mt++) {
            #pragma unroll
            for (int nt = 0; nt < 8; nt++) {
                const int i0 = rowbase + mt * 16 + trow;
                const int j0 = colbase + nt * 8 + tcol;
                smemT[(j0 + 0) * 132 + i0]     = acc[mt][nt][0];
                smemT[(j0 + 1) * 132 + i0]     = acc[mt][nt][1];
                smemT[(j0 + 0) * 132 + i0 + 8] = acc[mt][nt][2];
                smemT[(j0 + 1) * 132 + i0 + 8] = acc[mt][nt][3];
            }
        }
        __syncthreads();
        const int j    = tid >> 1;
        const int half = (tid & 1) * 64;
        float* dst = pS + (size_t)(n0 + j) * L + m0 + half;
        const float* srcrow = smemT + j * 132 + half;
        #pragma unroll
        for (int u = 0; u < 16; u++) {
            *(float4*)(dst + u * 4) = *(const float4*)(srcrow + u * 4);
        }
    }
}

// ---------------------------------------------------------------------------
// GEMM2: O = P @ Q. grid (D/128, L/128, B)
// ---------------------------------------------------------------------------
__global__ void __launch_bounds__(256)
gemm_pv_kernel(const __nv_bfloat16* __restrict__ Ph, const __nv_bfloat16* __restrict__ Pl,
               const __nv_bfloat16* __restrict__ Bh, const __nv_bfloat16* __restrict__ Bl,
               float* __restrict__ O) {
    extern __shared__ char smem[];
    const uint32_t sb = smem_to_u32(smem);
    const int tid = threadIdx.x, wid = tid >> 5, lid = tid & 31;
    const int b  = blockIdx.z;
    const int m0 = blockIdx.y * 128;
    const int n0 = blockIdx.x * 128;

    const __nv_bfloat16* pAh = Ph + (size_t)b * L * L;
    const __nv_bfloat16* pAl = Pl + (size_t)b * L * L;
    const __nv_bfloat16* pBh = Bh + (size_t)b * D * L;
    const __nv_bfloat16* pBl = Bl + (size_t)b * D * L;

    const int rowbase = (wid & 3) * 32;
    const int colbase = (wid >> 2) * 64;
    const int lrow = lid & 15;
    const uint32_t lkoff = (uint32_t)((lid >> 4) * 16);

    float acc[2][8][4];
    #pragma unroll
    for (int mt = 0; mt < 2; mt++)
        #pragma unroll
        for (int nt = 0; nt < 8; nt++)
            #pragma unroll
            for (int r = 0; r < 4; r++) acc[mt][nt][r] = 0.0f;

    gemm_mainloop(pAh, pAl, pBh, pBl, m0, n0, L, L, L,
                  sb, tid, rowbase, colbase, lrow, lkoff, acc);

    float* pO = O + (size_t)b * L * D;
    const int trow = lid >> 2;
    const int tcol = (lid & 3) * 2;
    #pragma unroll
    for (int mt = 0; mt < 2; mt++) {
        #pragma unroll
        for (int nt = 0; nt < 8; nt++) {
            const int row = m0 + rowbase + mt * 16 + trow;
            const int col = n0 + colbase + nt * 8 + tcol;
            *(float2*)(pO + (size_t)row * D + col) =
                make_float2(acc[mt][nt][0], acc[mt][nt][1]);
            *(float2*)(pO + (size_t)(row + 8) * D + col) =
                make_float2(acc[mt][nt][2], acc[mt][nt][3]);
        }
    }
}

// ---------------------------------------------------------------------------
// softmax in-place; emits P hi/lo bf16.
// ---------------------------------------------------------------------------
__global__ void __launch_bounds__(256) softmax_kernel(float* __restrict__ attn) {
    const size_t row = blockIdx.x;
    float* p = attn + row * L;
    __nv_bfloat16* ph = g_ph + row * L;
    __nv_bfloat16* pl = g_pl + row * L;
    const int tid = threadIdx.x;

    float4 v = ((const float4*)p)[tid];
    float m = fmaxf(fmaxf(v.x, v.y), fmaxf(v.z, v.w));
    #pragma unroll
    for (int o = 16; o > 0; o >>= 1) m = fmaxf(m, __shfl_xor_sync(0xffffffffu, m, o));

    __shared__ float smem[8];
    __shared__ float stat;
    const int wid = tid >> 5, lid = tid & 31;
    if (lid == 0) smem[wid] = m;
    __syncthreads();
    if (tid == 0) {
        float mm = smem[0];
        #pragma unroll
        for (int i = 1; i < 8; i++) mm = fmaxf(mm, smem[i]);
        stat = mm;
    }
    __syncthreads();
    const float rmax = stat;

    if (rmax == neg_inf()) {
        ((float4*)p)[tid] = make_float4(0.f, 0.f, 0.f, 0.f);
        const uint2 z = make_uint2(0u, 0u);
        ((uint2*)ph)[tid] = z;
        ((uint2*)pl)[tid] = z;
        return;
    }

    float4 e;
    e.x = __expf(v.x - rmax); e.y = __expf(v.y - rmax);
    e.z = __expf(v.z - rmax); e.w = __expf(v.w - rmax);
    float s = (e.x + e.y) + (e.z + e.w);
    #pragma unroll
    for (int o = 16; o > 0; o >>= 1) s += __shfl_xor_sync(0xffffffffu, s, o);
    if (lid == 0) smem[wid] = s;
    __syncthreads();
    if (tid == 0) {
        float ss = smem[0];
        #pragma unroll
        for (int i = 1; i < 8; i++) ss += smem[i];
        stat = 1.0f / ss;
    }
    __syncthreads();
    const float inv = stat;
    e.x *= inv; e.y *= inv; e.z *= inv; e.w *= inv;
    ((float4*)p)[tid] = e;

    __nv_bfloat16 h0 = __float2bfloat16(e.x), h1 = __float2bfloat16(e.y);
    __nv_bfloat16 h2 = __float2bfloat16(e.z), h3 = __float2bfloat16(e.w);
    __nv_bfloat16 l0 = __float2bfloat16(e.x - __bfloat162float(h0));
    __nv_bfloat16 l1 = __float2bfloat16(e.y - __bfloat162float(h1));
    __nv_bfloat16 l2 = __float2bfloat16(e.z - __bfloat162float(h2));
    __nv_bfloat16 l3 = __float2bfloat16(e.w - __bfloat162float(h3));
    __nv_bfloat162 hp0, hp1, lp0, lp1;
    hp0.x = h0; hp0.y = h1; hp1.x = h2; hp1.y = h3;
    lp0.x = l0; lp0.y = l1; lp1.x = l2; lp1.y = l3;
    ((__nv_bfloat162*)ph)[tid * 2]     = hp0;
    ((__nv_bfloat162*)ph)[tid * 2 + 1] = hp1;
    ((__nv_bfloat162*)pl)[tid * 2]     = lp0;
    ((__nv_bfloat162*)pl)[tid * 2 + 1] = lp1;
}

// ---------------------------------------------------------------------------
// Launch
// ---------------------------------------------------------------------------
extern "C" void kernel_launch(void* const* d_in, const int* in_sizes, int n_in,
                              void* d_out, int out_size) {
    const float* q = (const float*)d_in[0];
    float* out  = (float*)d_out;
    float* attn = (float*)d_out + (size_t)B * L * D;

    void *qh, *ql, *qth, *qtl, *ph, *pl;
    cudaGetSymbolAddress(&qh,  g_qh);
    cudaGetSymbolAddress(&ql,  g_ql);
    cudaGetSymbolAddress(&qth, g_qth);
    cudaGetSymbolAddress(&qtl, g_qtl);
    cudaGetSymbolAddress(&ph,  g_ph);
    cudaGetSymbolAddress(&pl,  g_pl);

    cudaFuncSetAttribute(gemm_qqt_sym_kernel, cudaFuncAttributeMaxDynamicSharedMemorySize, GEMM_SMEM);
    cudaFuncSetAttribute(gemm_pv_kernel,      cudaFuncAttributeMaxDynamicSharedMemorySize, GEMM_SMEM);

    dim3 gs(D / 32, L / 32, B);
    split_q_kernel<<<gs, dim3(32, 8)>>>(q);

    dim3 g1(36, 1, B);
    gemm_qqt_sym_kernel<<<g1, 256, GEMM_SMEM>>>(
        (const __nv_bfloat16*)qh, (const __nv_bfloat16*)ql, attn);

    softmax_kernel<<<B * L, 256>>>(attn);

    dim3 g2(D / 128, L / 128, B);
    gemm_pv_kernel<<<g2, 256, GEMM_SMEM>>>(
        (const __nv_bfloat16*)ph, (const __nv_bfloat16*)pl,
        (const __nv_bfloat16*)qth, (const __nv_bfloat16*)qtl, out);
}

// round 8
// speedup vs baseline: 2.5900x; 1.0602x over previous
#include <cuda_runtime.h>
#include <cuda_bf16.h>
#include <cstdint>

#define B   32
#define L   1024
#define D   256
#define INV_TEMP (1.0f/16.0f)

// ---------------------------------------------------------------------------
// Scratch
// ---------------------------------------------------------------------------
__device__ __nv_bfloat16 g_qh [B * L * D];
__device__ __nv_bfloat16 g_ql [B * L * D];
__device__ __nv_bfloat16 g_qth[B * D * L];
__device__ __nv_bfloat16 g_qtl[B * D * L];
__device__ __nv_bfloat16 g_ph [B * L * L];
__device__ __nv_bfloat16 g_pl [B * L * L];

// upper-triangle block pair decode (8x8 blocks -> 36 pairs)
__constant__ uint8_t c_bi[36] = {0,0,0,0,0,0,0,0, 1,1,1,1,1,1,1, 2,2,2,2,2,2,
                                 3,3,3,3,3, 4,4,4,4, 5,5,5, 6,6, 7};
__constant__ uint8_t c_bj[36] = {0,1,2,3,4,5,6,7, 1,2,3,4,5,6,7, 2,3,4,5,6,7,
                                 3,4,5,6,7, 4,5,6,7, 5,6,7, 6,7, 7};

__device__ __forceinline__ float neg_inf() { return __int_as_float(0xff800000); }

__device__ __forceinline__ uint32_t smem_to_u32(const void* p) {
    uint32_t a;
    asm("{ .reg .u64 t; cvta.to.shared.u64 t, %1; cvt.u32.u64 %0, t; }" : "=r"(a) : "l"(p));
    return a;
}

#define SWZ(x) ((x) ^ (((x) >> 3) & 0x70))

__device__ __forceinline__ void ldsm_x4(uint32_t& r0, uint32_t& r1, uint32_t& r2, uint32_t& r3,
                                        uint32_t addr) {
    asm volatile("ldmatrix.sync.aligned.m8n8.x4.shared.b16 {%0,%1,%2,%3}, [%4];"
                 : "=r"(r0), "=r"(r1), "=r"(r2), "=r"(r3) : "r"(addr));
}

__device__ __forceinline__ void mma_bf16(float& c0, float& c1, float& c2, float& c3,
                                         uint32_t a0, uint32_t a1, uint32_t a2, uint32_t a3,
                                         uint32_t b0, uint32_t b1) {
    asm volatile("mma.sync.aligned.m16n8k16.row.col.f32.bf16.bf16.f32 "
                 "{%0,%1,%2,%3}, {%4,%5,%6,%7}, {%8,%9}, {%0,%1,%2,%3};"
                 : "+f"(c0), "+f"(c1), "+f"(c2), "+f"(c3)
                 : "r"(a0), "r"(a1), "r"(a2), "r"(a3), "r"(b0), "r"(b1));
}

#define CP_ASYNC_16(dst, src) \
    asm volatile("cp.async.cg.shared.global [%0], [%1], 16;" :: "r"(dst), "l"(src))
#define CP_ASYNC_COMMIT() asm volatile("cp.async.commit_group;" ::: "memory")
#define CP_ASYNC_WAIT(n)  asm volatile("cp.async.wait_group %0;" :: "n"(n) : "memory")

// ---------------------------------------------------------------------------
// Kernel A: split q -> bf16 hi/lo + transposed hi/lo copies.
// ---------------------------------------------------------------------------
__global__ void __launch_bounds__(256) split_q_kernel(const float* __restrict__ q) {
    const int b  = blockIdx.z;
    const int d0 = blockIdx.x * 32;
    const int l0 = blockIdx.y * 32;
    const float* Q = q + (size_t)b * L * D;
    __shared__ float t[32][33];
    const int tx = threadIdx.x, ty = threadIdx.y;

    #pragma unroll
    for (int i = 0; i < 4; i++) {
        const int r = ty + i * 8;
        const float v = Q[(size_t)(l0 + r) * D + d0 + tx];
        t[r][tx] = v;
        __nv_bfloat16 h  = __float2bfloat16(v);
        __nv_bfloat16 lo = __float2bfloat16(v - __bfloat162float(h));
        const size_t idx = (size_t)b * L * D + (size_t)(l0 + r) * D + d0 + tx;
        g_qh[idx] = h;
        g_ql[idx] = lo;
    }
    __syncthreads();
    #pragma unroll
    for (int i = 0; i < 4; i++) {
        const int r = ty + i * 8;
        const float v = t[tx][r];
        __nv_bfloat16 h  = __float2bfloat16(v);
        __nv_bfloat16 lo = __float2bfloat16(v - __bfloat162float(h));
        const size_t idx = (size_t)b * D * L + (size_t)(d0 + r) * L + l0 + tx;
        g_qth[idx] = h;
        g_qtl[idx] = lo;
    }
}

// ---------------------------------------------------------------------------
// Generic tile loader: ROWS x 64 bf16, 128B swizzled rows.
// ---------------------------------------------------------------------------
template <int ROWS>
__device__ __forceinline__ void issue_tile(const __nv_bfloat16* __restrict__ src,
                                           int row0, int ld, int k0,
                                           uint32_t smem_tile, int tid) {
    #pragma unroll
    for (int i = 0; i < (ROWS * 8) / 256; i++) {
        const int chunk = tid + i * 256;
        const int row = chunk >> 3;
        const int c16 = chunk & 7;
        const __nv_bfloat16* g = src + (size_t)(row0 + row) * ld + k0 + c16 * 8;
        CP_ASYNC_16(smem_tile + SWZ((uint32_t)(row * 128 + c16 * 16)), g);
    }
}

// ===========================================================================
// GEMM1 (symmetric, unchanged from R7): CTA 128x128, 8 warps (4x2), 3-stage.
// ===========================================================================
#define TILE_BYTES 16384
#define STAGE_BYTES (4 * TILE_BYTES)
#define NSTAGE 3
#define GEMM1_SMEM (NSTAGE * STAGE_BYTES)

__device__ __forceinline__ void issue_stage128(
        const __nv_bfloat16* pAh, const __nv_bfloat16* pAl,
        const __nv_bfloat16* pBh, const __nv_bfloat16* pBl,
        int m0, int n0, int lda, int ldb, int k0,
        uint32_t st, int tid) {
    issue_tile<128>(pAh, m0, lda, k0, st + 0 * TILE_BYTES, tid);
    issue_tile<128>(pAl, m0, lda, k0, st + 1 * TILE_BYTES, tid);
    issue_tile<128>(pBh, n0, ldb, k0, st + 2 * TILE_BYTES, tid);
    issue_tile<128>(pBl, n0, ldb, k0, st + 3 * TILE_BYTES, tid);
    CP_ASYNC_COMMIT();
}

__global__ void __launch_bounds__(256)
gemm_qqt_sym_kernel(const __nv_bfloat16* __restrict__ Qh, const __nv_bfloat16* __restrict__ Ql,
                    float* __restrict__ S) {
    extern __shared__ char smem[];
    const uint32_t sb = smem_to_u32(smem);
    const int tid = threadIdx.x, wid = tid >> 5, lid = tid & 31;
    const int b  = blockIdx.z;
    const int bi = c_bi[blockIdx.x];
    const int bj = c_bj[blockIdx.x];
    const int m0 = bi * 128;
    const int n0 = bj * 128;

    const __nv_bfloat16* pAh = Qh + (size_t)b * L * D;
    const __nv_bfloat16* pAl = Ql + (size_t)b * L * D;

    const int rowbase = (wid & 3) * 32;
    const int colbase = (wid >> 2) * 64;
    const int lrow = lid & 15;
    const uint32_t lkoff = (uint32_t)((lid >> 4) * 16);

    float acc[2][8][4];
    #pragma unroll
    for (int mt = 0; mt < 2; mt++)
        #pragma unroll
        for (int nt = 0; nt < 8; nt++)
            #pragma unroll
            for (int r = 0; r < 4; r++) acc[mt][nt][r] = 0.0f;

    const int nch = D >> 6;   // 4
    issue_stage128(pAh, pAl, pAh, pAl, m0, n0, D, D, 0, sb, tid);
    issue_stage128(pAh, pAl, pAh, pAl, m0, n0, D, D, 64, sb + STAGE_BYTES, tid);

    for (int c = 0; c < nch; c++) {
        if (c + 1 < nch) { CP_ASYNC_WAIT(1); } else { CP_ASYNC_WAIT(0); }
        __syncthreads();
        if (c + 2 < nch) {
            issue_stage128(pAh, pAl, pAh, pAl, m0, n0, D, D, (c + 2) << 6,
                           sb + (uint32_t)((c + 2) % NSTAGE) * STAGE_BYTES, tid);
        }

        const uint32_t st = sb + (uint32_t)(c % NSTAGE) * STAGE_BYTES;
        const uint32_t aH = st + 0 * TILE_BYTES;
        const uint32_t aL = st + 1 * TILE_BYTES;
        const uint32_t bH = st + 2 * TILE_BYTES;
        const uint32_t bL = st + 3 * TILE_BYTES;

        #pragma unroll
        for (int ks = 0; ks < 4; ks++) {
            const uint32_t kb = (uint32_t)(ks * 32) + lkoff;
            uint32_t ah[2][4], al[2][4];
            #pragma unroll
            for (int mt = 0; mt < 2; mt++) {
                const uint32_t boff = (uint32_t)((rowbase + mt * 16 + lrow) * 128) + kb;
                ldsm_x4(ah[mt][0], ah[mt][1], ah[mt][2], ah[mt][3], aH + SWZ(boff));
                ldsm_x4(al[mt][0], al[mt][1], al[mt][2], al[mt][3], aL + SWZ(boff));
            }
            #pragma unroll
            for (int np = 0; np < 4; np++) {
                const uint32_t boff = (uint32_t)((colbase + np * 16 + lrow) * 128) + kb;
                uint32_t bh[4], bl[4];
                ldsm_x4(bh[0], bh[1], bh[2], bh[3], bH + SWZ(boff));
                ldsm_x4(bl[0], bl[1], bl[2], bl[3], bL + SWZ(boff));
                #pragma unroll
                for (int mt = 0; mt < 2; mt++) {
                    float* c0 = acc[mt][np * 2 + 0];
                    float* c1 = acc[mt][np * 2 + 1];
                    mma_bf16(c0[0], c0[1], c0[2], c0[3],
                             ah[mt][0], ah[mt][1], ah[mt][2], ah[mt][3], bh[0], bh[2]);
                    mma_bf16(c1[0], c1[1], c1[2], c1[3],
                             ah[mt][0], ah[mt][1], ah[mt][2], ah[mt][3], bh[1], bh[3]);
                    mma_bf16(c0[0], c0[1], c0[2], c0[3],
                             ah[mt][0], ah[mt][1], ah[mt][2], ah[mt][3], bl[0], bl[2]);
                    mma_bf16(c1[0], c1[1], c1[2], c1[3],
                             ah[mt][0], ah[mt][1], ah[mt][2], ah[mt][3], bl[1], bl[3]);
                    mma_bf16(c0[0], c0[1], c0[2], c0[3],
                             al[mt][0], al[mt][1], al[mt][2], al[mt][3], bh[0], bh[2]);
                    mma_bf16(c1[0], c1[1], c1[2], c1[3],
                             al[mt][0], al[mt][1], al[mt][2], al[mt][3], bh[1], bh[3]);
                }
            }
        }
    }
    __syncthreads();

    #pragma unroll
    for (int mt = 0; mt < 2; mt++)
        #pragma unroll
        for (int nt = 0; nt < 8; nt++)
            #pragma unroll
            for (int r = 0; r < 4; r++) {
                float v = acc[mt][nt][r];
                acc[mt][nt][r] = (v == 0.0f) ? neg_inf() : v * INV_TEMP;
            }

    float* pS = S + (size_t)b * L * L;
    const int trow = lid >> 2;
    const int tcol = (lid & 3) * 2;

    #pragma unroll
    for (int mt = 0; mt < 2; mt++) {
        #pragma unroll
        for (int nt = 0; nt < 8; nt++) {
            const int row = m0 + rowbase + mt * 16 + trow;
            const int col = n0 + colbase + nt * 8 + tcol;
            *(float2*)(pS + (size_t)row * L + col) =
                make_float2(acc[mt][nt][0], acc[mt][nt][1]);
            *(float2*)(pS + (size_t)(row + 8) * L + col) =
                make_float2(acc[mt][nt][2], acc[mt][nt][3]);
        }
    }

    if (bi != bj) {
        float* smemT = (float*)smem;
        #pragma unroll
        for (int mt = 0; mt < 2; mt++) {
            #pragma unroll
            for (int nt = 0; nt < 8; nt++) {
                const int i0 = rowbase + mt * 16 + trow;
                const int j0 = colbase + nt * 8 + tcol;
                smemT[(j0 + 0) * 132 + i0]     = acc[mt][nt][0];
                smemT[(j0 + 1) * 132 + i0]     = acc[mt][nt][1];
                smemT[(j0 + 0) * 132 + i0 + 8] = acc[mt][nt][2];
                smemT[(j0 + 1) * 132 + i0 + 8] = acc[mt][nt][3];
            }
        }
        __syncthreads();
        const int j    = tid >> 1;
        const int half = (tid & 1) * 64;
        float* dst = pS + (size_t)(n0 + j) * L + m0 + half;
        const float* srcrow = smemT + j * 132 + half;
        #pragma unroll
        for (int u = 0; u < 16; u++) {
            *(float4*)(dst + u * 4) = *(const float4*)(srcrow + u * 4);
        }
    }
}

// ===========================================================================
// GEMM2 (NEW): O = P @ Q. CTA 64x128, 8 warps (2x4), warp tile 32x32,
// K chunk 64, 2-stage. smem/stage = A 16KB + B 32KB = 48KB; 96KB total ->
// 2 CTAs/SM (launch_bounds(256,2), reg target 128).
// grid (D/128, L/64, B) = (2, 16, 32)
// ===========================================================================
#define PV_TA 8192                       // 64 x 128B
#define PV_TB 16384                      // 128 x 128B
#define PV_STAGE (2 * PV_TA + 2 * PV_TB) // 48KB
#define PV_SMEM (2 * PV_STAGE)           // 96KB
#define PV_AH 0
#define PV_AL PV_TA
#define PV_BH (2 * PV_TA)
#define PV_BL (2 * PV_TA + PV_TB)

__device__ __forceinline__ void pv_issue_stage(
        const __nv_bfloat16* pAh, const __nv_bfloat16* pAl,
        const __nv_bfloat16* pBh, const __nv_bfloat16* pBl,
        int m0, int n0, int k0, uint32_t st, int tid) {
    issue_tile<64>(pAh, m0, L, k0, st + PV_AH, tid);
    issue_tile<64>(pAl, m0, L, k0, st + PV_AL, tid);
    issue_tile<128>(pBh, n0, L, k0, st + PV_BH, tid);
    issue_tile<128>(pBl, n0, L, k0, st + PV_BL, tid);
    CP_ASYNC_COMMIT();
}

__global__ void __launch_bounds__(256, 2)
gemm_pv_kernel(const __nv_bfloat16* __restrict__ Ph, const __nv_bfloat16* __restrict__ Pl,
               const __nv_bfloat16* __restrict__ Bh, const __nv_bfloat16* __restrict__ Bl,
               float* __restrict__ O) {
    extern __shared__ char smem[];
    const uint32_t sb = smem_to_u32(smem);
    const int tid = threadIdx.x, wid = tid >> 5, lid = tid & 31;
    const int b  = blockIdx.z;
    const int m0 = blockIdx.y * 64;
    const int n0 = blockIdx.x * 128;

    const __nv_bfloat16* pAh = Ph + (size_t)b * L * L;
    const __nv_bfloat16* pAl = Pl + (size_t)b * L * L;
    const __nv_bfloat16* pBh = Bh + (size_t)b * D * L;
    const __nv_bfloat16* pBl = Bl + (size_t)b * D * L;

    const int rowbase = (wid & 1) * 32;      // 2 row groups
    const int colbase = (wid >> 1) * 32;     // 4 col groups
    const int lrow = lid & 15;
    const uint32_t lkoff = (uint32_t)((lid >> 4) * 16);

    float acc[2][4][4];
    #pragma unroll
    for (int mt = 0; mt < 2; mt++)
        #pragma unroll
        for (int nt = 0; nt < 4; nt++)
            #pragma unroll
            for (int r = 0; r < 4; r++) acc[mt][nt][r] = 0.0f;

    const int nch = L >> 6;   // 16

    pv_issue_stage(pAh, pAl, pBh, pBl, m0, n0, 0, sb, tid);

    for (int c = 0; c < nch; c++) {
        if (c + 1 < nch) {
            pv_issue_stage(pAh, pAl, pBh, pBl, m0, n0, (c + 1) << 6,
                           sb + (uint32_t)((c + 1) & 1) * PV_STAGE, tid);
            CP_ASYNC_WAIT(1);
        } else {
            CP_ASYNC_WAIT(0);
        }
        __syncthreads();

        const uint32_t st = sb + (uint32_t)(c & 1) * PV_STAGE;
        const uint32_t aH = st + PV_AH;
        const uint32_t aL = st + PV_AL;
        const uint32_t bH = st + PV_BH;
        const uint32_t bL = st + PV_BL;

        #pragma unroll
        for (int ks = 0; ks < 4; ks++) {
            const uint32_t kb = (uint32_t)(ks * 32) + lkoff;
            uint32_t ah[2][4], al[2][4];
            #pragma unroll
            for (int mt = 0; mt < 2; mt++) {
                const uint32_t boff = (uint32_t)((rowbase + mt * 16 + lrow) * 128) + kb;
                ldsm_x4(ah[mt][0], ah[mt][1], ah[mt][2], ah[mt][3], aH + SWZ(boff));
                ldsm_x4(al[mt][0], al[mt][1], al[mt][2], al[mt][3], aL + SWZ(boff));
            }
            #pragma unroll
            for (int np = 0; np < 2; np++) {
                const uint32_t boff = (uint32_t)((colbase + np * 16 + lrow) * 128) + kb;
                uint32_t bh[4], bl[4];
                ldsm_x4(bh[0], bh[1], bh[2], bh[3], bH + SWZ(boff));
                ldsm_x4(bl[0], bl[1], bl[2], bl[3], bL + SWZ(boff));
                #pragma unroll
                for (int mt = 0; mt < 2; mt++) {
                    float* c0 = acc[mt][np * 2 + 0];
                    float* c1 = acc[mt][np * 2 + 1];
                    mma_bf16(c0[0], c0[1], c0[2], c0[3],
                             ah[mt][0], ah[mt][1], ah[mt][2], ah[mt][3], bh[0], bh[2]);
                    mma_bf16(c1[0], c1[1], c1[2], c1[3],
                             ah[mt][0], ah[mt][1], ah[mt][2], ah[mt][3], bh[1], bh[3]);
                    mma_bf16(c0[0], c0[1], c0[2], c0[3],
                             ah[mt][0], ah[mt][1], ah[mt][2], ah[mt][3], bl[0], bl[2]);
                    mma_bf16(c1[0], c1[1], c1[2], c1[3],
                             ah[mt][0], ah[mt][1], ah[mt][2], ah[mt][3], bl[1], bl[3]);
                    mma_bf16(c0[0], c0[1], c0[2], c0[3],
                             al[mt][0], al[mt][1], al[mt][2], al[mt][3], bh[0], bh[2]);
                    mma_bf16(c1[0], c1[1], c1[2], c1[3],
                             al[mt][0], al[mt][1], al[mt][2], al[mt][3], bh[1], bh[3]);
                }
            }
        }
        __syncthreads();
    }

    float* pO = O + (size_t)b * L * D;
    const int trow = lid >> 2;
    const int tcol = (lid & 3) * 2;
    #pragma unroll
    for (int mt = 0; mt < 2; mt++) {
        #pragma unroll
        for (int nt = 0; nt < 4; nt++) {
            const int row = m0 + rowbase + mt * 16 + trow;
            const int col = n0 + colbase + nt * 8 + tcol;
            *(float2*)(pO + (size_t)row * D + col) =
                make_float2(acc[mt][nt][0], acc[mt][nt][1]);
            *(float2*)(pO + (size_t)(row + 8) * D + col) =
                make_float2(acc[mt][nt][2], acc[mt][nt][3]);
        }
    }
}

// ---------------------------------------------------------------------------
// softmax in-place; emits P hi/lo bf16.
// ---------------------------------------------------------------------------
__global__ void __launch_bounds__(256) softmax_kernel(float* __restrict__ attn) {
    const size_t row = blockIdx.x;
    float* p = attn + row * L;
    __nv_bfloat16* ph = g_ph + row * L;
    __nv_bfloat16* pl = g_pl + row * L;
    const int tid = threadIdx.x;

    float4 v = ((const float4*)p)[tid];
    float m = fmaxf(fmaxf(v.x, v.y), fmaxf(v.z, v.w));
    #pragma unroll
    for (int o = 16; o > 0; o >>= 1) m = fmaxf(m, __shfl_xor_sync(0xffffffffu, m, o));

    __shared__ float smem[8];
    __shared__ float stat;
    const int wid = tid >> 5, lid = tid & 31;
    if (lid == 0) smem[wid] = m;
    __syncthreads();
    if (tid == 0) {
        float mm = smem[0];
        #pragma unroll
        for (int i = 1; i < 8; i++) mm = fmaxf(mm, smem[i]);
        stat = mm;
    }
    __syncthreads();
    const float rmax = stat;

    if (rmax == neg_inf()) {
        ((float4*)p)[tid] = make_float4(0.f, 0.f, 0.f, 0.f);
        const uint2 z = make_uint2(0u, 0u);
        ((uint2*)ph)[tid] = z;
        ((uint2*)pl)[tid] = z;
        return;
    }

    float4 e;
    e.x = __expf(v.x - rmax); e.y = __expf(v.y - rmax);
    e.z = __expf(v.z - rmax); e.w = __expf(v.w - rmax);
    float s = (e.x + e.y) + (e.z + e.w);
    #pragma unroll
    for (int o = 16; o > 0; o >>= 1) s += __shfl_xor_sync(0xffffffffu, s, o);
    if (lid == 0) smem[wid] = s;
    __syncthreads();
    if (tid == 0) {
        float ss = smem[0];
        #pragma unroll
        for (int i = 1; i < 8; i++) ss += smem[i];
        stat = 1.0f / ss;
    }
    __syncthreads();
    const float inv = stat;
    e.x *= inv; e.y *= inv; e.z *= inv; e.w *= inv;
    ((float4*)p)[tid] = e;

    __nv_bfloat16 h0 = __float2bfloat16(e.x), h1 = __float2bfloat16(e.y);
    __nv_bfloat16 h2 = __float2bfloat16(e.z), h3 = __float2bfloat16(e.w);
    __nv_bfloat16 l0 = __float2bfloat16(e.x - __bfloat162float(h0));
    __nv_bfloat16 l1 = __float2bfloat16(e.y - __bfloat162float(h1));
    __nv_bfloat16 l2 = __float2bfloat16(e.z - __bfloat162float(h2));
    __nv_bfloat16 l3 = __float2bfloat16(e.w - __bfloat162float(h3));
    __nv_bfloat162 hp0, hp1, lp0, lp1;
    hp0.x = h0; hp0.y = h1; hp1.x = h2; hp1.y = h3;
    lp0.x = l0; lp0.y = l1; lp1.x = l2; lp1.y = l3;
    ((__nv_bfloat162*)ph)[tid * 2]     = hp0;
    ((__nv_bfloat162*)ph)[tid * 2 + 1] = hp1;
    ((__nv_bfloat162*)pl)[tid * 2]     = lp0;
    ((__nv_bfloat162*)pl)[tid * 2 + 1] = lp1;
}

// ---------------------------------------------------------------------------
// Launch
// ---------------------------------------------------------------------------
extern "C" void kernel_launch(void* const* d_in, const int* in_sizes, int n_in,
                              void* d_out, int out_size) {
    const float* q = (const float*)d_in[0];
    float* out  = (float*)d_out;
    float* attn = (float*)d_out + (size_t)B * L * D;

    void *qh, *ql, *qth, *qtl, *ph, *pl;
    cudaGetSymbolAddress(&qh,  g_qh);
    cudaGetSymbolAddress(&ql,  g_ql);
    cudaGetSymbolAddress(&qth, g_qth);
    cudaGetSymbolAddress(&qtl, g_qtl);
    cudaGetSymbolAddress(&ph,  g_ph);
    cudaGetSymbolAddress(&pl,  g_pl);

    cudaFuncSetAttribute(gemm_qqt_sym_kernel, cudaFuncAttributeMaxDynamicSharedMemorySize, GEMM1_SMEM);
    cudaFuncSetAttribute(gemm_pv_kernel,      cudaFuncAttributeMaxDynamicSharedMemorySize, PV_SMEM);

    dim3 gs(D / 32, L / 32, B);
    split_q_kernel<<<gs, dim3(32, 8)>>>(q);

    dim3 g1(36, 1, B);
    gemm_qqt_sym_kernel<<<g1, 256, GEMM1_SMEM>>>(
        (const __nv_bfloat16*)qh, (const __nv_bfloat16*)ql, attn);

    softmax_kernel<<<B * L, 256>>>(attn);

    dim3 g2(D / 128, L / 64, B);   // (2, 16, 32)
    gemm_pv_kernel<<<g2, 256, PV_SMEM>>>(
        (const __nv_bfloat16*)ph, (const __nv_bfloat16*)pl,
        (const __nv_bfloat16*)qth, (const __nv_bfloat16*)qtl, out);
}